// round 2
// baseline (speedup 1.0000x reference)
#include <cuda_runtime.h>

#define NNODES 50000
#define EDGES  400000
#define DD     128
#define HH     256
#define LL     5
#define BOND_ROWS 13

// ---------------- scratch (device globals; no allocation) ----------------
__device__ float g_agg[(size_t)NNODES * DD];   // (1+eps)*h + sum of messages
__device__ float g_y  [(size_t)NNODES * HH];   // GEMM1 output
__device__ float g_z2 [(size_t)NNODES * DD];   // GEMM2 output
__device__ float g_h  [(size_t)NNODES * DD];   // current node features (layers >= 1)
__device__ float g_sum1[HH], g_sq1[HH];
__device__ float g_sum2[DD], g_sq2[DD];
__device__ float g_scale2[DD], g_shift2[DD];

// ---------------- helpers ----------------
__device__ __forceinline__ void red_add_v4(float* addr, float4 v) {
    asm volatile("red.global.add.v4.f32 [%0], {%1,%2,%3,%4};"
                 :: "l"(addr), "f"(v.x), "f"(v.y), "f"(v.z), "f"(v.w)
                 : "memory");
}

// ---------------- kernels ----------------

__global__ void zero_stats_kernel() {
    int t = threadIdx.x;
    if (t < HH) { g_sum1[t] = 0.f; g_sq1[t] = 0.f; }
    if (t < DD) { g_sum2[t] = 0.f; g_sq2[t] = 0.f; }
}

// agg = (1 + eps[l]) * h
__global__ void init_agg_kernel(const float* __restrict__ h,
                                const float* __restrict__ eps, int l) {
    int i = blockIdx.x * blockDim.x + threadIdx.x;
    const int n4 = NNODES * DD / 4;
    if (i >= n4) return;
    float c = 1.f + __ldg(eps + l);
    float4 v = __ldg((const float4*)h + i);
    v.x *= c; v.y *= c; v.z *= c; v.w *= c;
    ((float4*)g_agg)[i] = v;
}

// message = relu(h[src] + bond_emb[a0] + bond_emb[5+a1] + bond_emb[11+a2])
// scatter-add to g_agg[dst].  One warp per edge, float4 per lane.
__global__ void __launch_bounds__(256)
edge_kernel(const float* __restrict__ h,
            const int* __restrict__ src, const int* __restrict__ dst,
            const int* __restrict__ ea, const float* __restrict__ bond) {
    int warp  = (blockIdx.x * blockDim.x + threadIdx.x) >> 5;
    int lane  = threadIdx.x & 31;
    int nwarp = (gridDim.x * blockDim.x) >> 5;
    for (int e = warp; e < EDGES; e += nwarp) {
        int s  = __ldg(src + e);
        int d  = __ldg(dst + e);
        int a0 = __ldg(ea + 3 * e + 0);
        int a1 = __ldg(ea + 3 * e + 1);
        int a2 = __ldg(ea + 3 * e + 2);
        float4 v  = __ldg((const float4*)(h + (size_t)s * DD) + lane);
        float4 e0 = __ldg((const float4*)(bond + (size_t)(a0)      * DD) + lane);
        float4 e1 = __ldg((const float4*)(bond + (size_t)(5 + a1)  * DD) + lane);
        float4 e2 = __ldg((const float4*)(bond + (size_t)(11 + a2) * DD) + lane);
        v.x = fmaxf(v.x + e0.x + e1.x + e2.x, 0.f);
        v.y = fmaxf(v.y + e0.y + e1.y + e2.y, 0.f);
        v.z = fmaxf(v.z + e0.z + e1.z + e2.z, 0.f);
        v.w = fmaxf(v.w + e0.w + e1.w + e2.w, 0.f);
        red_add_v4(g_agg + (size_t)d * DD + lane * 4, v);
    }
}

// Register-tiled fp32 GEMM: C[M,NC] = A[M,K] @ B[K,NC] + bias.
// If BNA: A is transformed on load: a' = relu(a*scale[k] + shift[k])
// with scale/shift derived from (bsum,bsq,gamma,beta) batch stats.
template<int K, int NC, bool BNA>
__global__ void __launch_bounds__(256)
gemm_kernel(const float* __restrict__ A, const float* __restrict__ B,
            const float* __restrict__ bias, float* __restrict__ C, int M,
            const float* __restrict__ bsum, const float* __restrict__ bsq,
            const float* __restrict__ gam,  const float* __restrict__ bet) {
    constexpr int BM = 128, BNN = 64, BK = 16, TM = 8, TN = 4;
    __shared__ float As[BK][BM + 4];
    __shared__ float Bs[BK][BNN];
    __shared__ float ssc[K], ssh[K];

    int tid = threadIdx.x;
    if (BNA) {
        float invM = 1.f / (float)M;
        for (int k = tid; k < K; k += 256) {
            float mu  = bsum[k] * invM;
            float var = bsq[k] * invM - mu * mu;
            float s   = gam[k] * rsqrtf(var + 1e-5f);
            ssc[k] = s;
            ssh[k] = bet[k] - mu * s;
        }
        __syncthreads();
    }

    int bm = blockIdx.x * BM;
    int bn = blockIdx.y * BNN;
    int ty = tid >> 4;      // 0..15
    int tx = tid & 15;      // 0..15

    float acc[TM][TN];
#pragma unroll
    for (int i = 0; i < TM; ++i)
#pragma unroll
        for (int j = 0; j < TN; ++j) acc[i][j] = 0.f;

    for (int k0 = 0; k0 < K; k0 += BK) {
        // --- load A tile (BM x BK), transposed into As ---
#pragma unroll
        for (int it = 0; it < 2; ++it) {
            int f4 = tid * 2 + it;          // 0..511
            int r  = f4 >> 2;               // 0..127
            int c4 = f4 & 3;                // 0..3
            int gr = bm + r;
            float4 v = make_float4(0.f, 0.f, 0.f, 0.f);
            if (gr < M)
                v = __ldg((const float4*)(A + (size_t)gr * K + k0 + c4 * 4));
            if (BNA) {
                int kk = k0 + c4 * 4;
                v.x = fmaxf(fmaf(v.x, ssc[kk + 0], ssh[kk + 0]), 0.f);
                v.y = fmaxf(fmaf(v.y, ssc[kk + 1], ssh[kk + 1]), 0.f);
                v.z = fmaxf(fmaf(v.z, ssc[kk + 2], ssh[kk + 2]), 0.f);
                v.w = fmaxf(fmaf(v.w, ssc[kk + 3], ssh[kk + 3]), 0.f);
            }
            As[c4 * 4 + 0][r] = v.x;
            As[c4 * 4 + 1][r] = v.y;
            As[c4 * 4 + 2][r] = v.z;
            As[c4 * 4 + 3][r] = v.w;
        }
        // --- load B tile (BK x BNN) ---
        {
            int r  = tid >> 4;   // 0..15
            int c4 = tid & 15;   // 0..15
            float4 v = __ldg((const float4*)(B + (size_t)(k0 + r) * NC + bn + c4 * 4));
            *(float4*)&Bs[r][c4 * 4] = v;
        }
        __syncthreads();

#pragma unroll
        for (int kk = 0; kk < BK; ++kk) {
            float a[TM];
#pragma unroll
            for (int i = 0; i < TM; ++i) a[i] = As[kk][ty * TM + i];
            float4 b4 = *(const float4*)&Bs[kk][tx * TN];
            float b[TN] = {b4.x, b4.y, b4.z, b4.w};
#pragma unroll
            for (int i = 0; i < TM; ++i)
#pragma unroll
                for (int j = 0; j < TN; ++j)
                    acc[i][j] = fmaf(a[i], b[j], acc[i][j]);
        }
        __syncthreads();
    }

    // --- epilogue: + bias, store float4 ---
    float4 bb;
    bb.x = __ldg(bias + bn + tx * 4 + 0);
    bb.y = __ldg(bias + bn + tx * 4 + 1);
    bb.z = __ldg(bias + bn + tx * 4 + 2);
    bb.w = __ldg(bias + bn + tx * 4 + 3);
#pragma unroll
    for (int i = 0; i < TM; ++i) {
        int gr = bm + ty * TM + i;
        if (gr < M) {
            float4 o;
            o.x = acc[i][0] + bb.x;
            o.y = acc[i][1] + bb.y;
            o.z = acc[i][2] + bb.z;
            o.w = acc[i][3] + bb.w;
            *(float4*)(C + (size_t)gr * NC + bn + tx * 4) = o;
        }
    }
}

// column sums / sum-of-squares of A[M,C] -> atomics into sum/sq
template<int C>
__global__ void col_stats_kernel(const float* __restrict__ A, int M,
                                 float* __restrict__ sum, float* __restrict__ sq) {
    int t  = threadIdx.x;            // blockDim.x == C
    int r0 = blockIdx.x * 256;
    int re = min(r0 + 256, M);
    float s = 0.f, q = 0.f;
    for (int r = r0; r < re; ++r) {
        float v = __ldg(A + (size_t)r * C + t);
        s += v;
        q = fmaf(v, v, q);
    }
    atomicAdd(sum + t, s);
    atomicAdd(sq + t, q);
}

// scale/shift for outer BN (D columns)
__global__ void bn2_finalize_kernel(const float* __restrict__ gam,
                                    const float* __restrict__ bet, float invM) {
    int t = threadIdx.x;
    if (t < DD) {
        float mu  = g_sum2[t] * invM;
        float var = g_sq2[t] * invM - mu * mu;
        float s   = __ldg(gam + t) * rsqrtf(var + 1e-5f);
        g_scale2[t] = s;
        g_shift2[t] = __ldg(bet + t) - mu * s;
    }
}

// out = bn2(z2) [+ relu]
__global__ void bn2_apply_kernel(const float* __restrict__ z,
                                 float* __restrict__ out, int do_relu) {
    int i = blockIdx.x * blockDim.x + threadIdx.x;
    const int n4 = NNODES * DD / 4;
    if (i >= n4) return;
    int c = (i & (DD / 4 - 1)) << 2;   // column of first element
    float4 v = __ldg((const float4*)z + i);
    v.x = fmaf(v.x, g_scale2[c + 0], g_shift2[c + 0]);
    v.y = fmaf(v.y, g_scale2[c + 1], g_shift2[c + 1]);
    v.z = fmaf(v.z, g_scale2[c + 2], g_shift2[c + 2]);
    v.w = fmaf(v.w, g_scale2[c + 3], g_shift2[c + 3]);
    if (do_relu) {
        v.x = fmaxf(v.x, 0.f); v.y = fmaxf(v.y, 0.f);
        v.z = fmaxf(v.z, 0.f); v.w = fmaxf(v.w, 0.f);
    }
    ((float4*)out)[i] = v;
}

// ---------------- host launcher ----------------
extern "C" void kernel_launch(void* const* d_in, const int* in_sizes, int n_in,
                              void* d_out, int out_size) {
    const float* x    = (const float*)d_in[0];
    const int*   ei   = (const int*)  d_in[1];   // [2,E]
    const int*   ea   = (const int*)  d_in[2];   // [E,3]
    const float* W1   = (const float*)d_in[3];   // [L,D,H]
    const float* b1   = (const float*)d_in[4];   // [L,H]
    const float* g1   = (const float*)d_in[5];
    const float* bb1  = (const float*)d_in[6];
    const float* W2   = (const float*)d_in[7];   // [L,H,D]
    const float* b2   = (const float*)d_in[8];
    const float* eps  = (const float*)d_in[9];
    const float* bond = (const float*)d_in[10];  // [L,13,D]
    const float* g2   = (const float*)d_in[11];
    const float* bb2  = (const float*)d_in[12];
    float* out = (float*)d_out;

    // FIX (round 1 bug): __device__ symbols must be resolved via
    // cudaGetSymbolAddress before being passed as kernel arguments.
    // Passing `g_sum1` directly from host code silently used the host
    // shadow variable's address (GPU-writable on GB300 via ATS!).
    float *p_agg, *p_y, *p_z2, *p_h;
    float *p_sum1, *p_sq1, *p_sum2, *p_sq2;
    cudaGetSymbolAddress((void**)&p_agg,  g_agg);
    cudaGetSymbolAddress((void**)&p_y,    g_y);
    cudaGetSymbolAddress((void**)&p_z2,   g_z2);
    cudaGetSymbolAddress((void**)&p_h,    g_h);
    cudaGetSymbolAddress((void**)&p_sum1, g_sum1);
    cudaGetSymbolAddress((void**)&p_sq1,  g_sq1);
    cudaGetSymbolAddress((void**)&p_sum2, g_sum2);
    cudaGetSymbolAddress((void**)&p_sq2,  g_sq2);

    const int M = NNODES;
    const int ew_blocks = (NNODES * DD / 4 + 255) / 256;        // 6250
    const int st_blocks = (M + 255) / 256;                      // 196
    const dim3 g1grid((M + 127) / 128, HH / 64);                // 391 x 4
    const dim3 g2grid((M + 127) / 128, DD / 64);                // 391 x 2
    const float invM = 1.f / (float)M;

    const float* hcur = x;
    for (int l = 0; l < LL; ++l) {
        zero_stats_kernel<<<1, 256>>>();
        init_agg_kernel<<<ew_blocks, 256>>>(hcur, eps, l);
        edge_kernel<<<1024, 256>>>(hcur, ei, ei + EDGES, ea,
                                   bond + (size_t)l * BOND_ROWS * DD);
        // GEMM1: y = agg @ W1[l] + b1[l]
        gemm_kernel<DD, HH, false><<<g1grid, 256>>>(
            p_agg, W1 + (size_t)l * DD * HH, b1 + (size_t)l * HH, p_y, M,
            nullptr, nullptr, nullptr, nullptr);
        // BN1 stats over y columns
        col_stats_kernel<HH><<<st_blocks, HH>>>(p_y, M, p_sum1, p_sq1);
        // GEMM2 with fused BN1+ReLU on A: z2 = act(y) @ W2[l] + b2[l]
        gemm_kernel<HH, DD, true><<<g2grid, 256>>>(
            p_y, W2 + (size_t)l * HH * DD, b2 + (size_t)l * DD, p_z2, M,
            p_sum1, p_sq1, g1 + (size_t)l * HH, bb1 + (size_t)l * HH);
        // BN2 stats + finalize
        col_stats_kernel<DD><<<st_blocks, DD>>>(p_z2, M, p_sum2, p_sq2);
        bn2_finalize_kernel<<<1, 128>>>(g2 + (size_t)l * DD,
                                        bb2 + (size_t)l * DD, invM);
        // apply BN2 (+relu except last layer); last layer -> d_out
        float* dst = (l == LL - 1) ? out : p_h;
        bn2_apply_kernel<<<ew_blocks, 256>>>(p_z2, dst, (l < LL - 1) ? 1 : 0);
        hcur = p_h;
    }
}

// round 4
// speedup vs baseline: 1.0543x; 1.0543x over previous
#include <cuda_runtime.h>
#include <cstdint>

#define NNODES 50000
#define EDGES  400000
#define DD     128
#define HH     256
#define LL     5
#define BOND_ROWS 13

// ---------------- scratch (device globals; no allocation) ----------------
__device__ float g_agg[(size_t)NNODES * DD];
__device__ float g_y  [(size_t)NNODES * HH];
__device__ float g_z2 [(size_t)NNODES * DD];
__device__ float g_h  [(size_t)NNODES * DD];
__device__ float g_sum1[HH], g_sq1[HH];
__device__ float g_sum2[DD], g_sq2[DD];
__device__ float g_scale2[DD], g_shift2[DD];

// ---------------- helpers ----------------
__device__ __forceinline__ void red_add_v4(float* addr, float4 v) {
    asm volatile("red.global.add.v4.f32 [%0], {%1,%2,%3,%4};"
                 :: "l"(addr), "f"(v.x), "f"(v.y), "f"(v.z), "f"(v.w)
                 : "memory");
}
__device__ __forceinline__ uint32_t f2tf(float f) {
    uint32_t u;
    asm("cvt.rna.tf32.f32 %0, %1;" : "=r"(u) : "f"(f));
    return u;
}
// split: hi = tf32(a), lo = tf32(a - hi)
__device__ __forceinline__ void tf_split(float a, uint32_t& hi, uint32_t& lo) {
    hi = f2tf(a);
    lo = f2tf(a - __uint_as_float(hi));
}
__device__ __forceinline__ void mma_tf32(float* c, const uint32_t* a, const uint32_t* b) {
    asm volatile(
        "mma.sync.aligned.m16n8k8.row.col.f32.tf32.tf32.f32 "
        "{%0,%1,%2,%3}, {%4,%5,%6,%7}, {%8,%9}, {%0,%1,%2,%3};"
        : "+f"(c[0]), "+f"(c[1]), "+f"(c[2]), "+f"(c[3])
        : "r"(a[0]), "r"(a[1]), "r"(a[2]), "r"(a[3]), "r"(b[0]), "r"(b[1]));
}

// ---------------- small kernels ----------------
__global__ void zero_stats_kernel() {
    int t = threadIdx.x;
    if (t < HH) { g_sum1[t] = 0.f; g_sq1[t] = 0.f; }
    if (t < DD) { g_sum2[t] = 0.f; g_sq2[t] = 0.f; }
}

// agg = (1 + eps[0]) * x   (layer 0 only; later layers fused into bn2_apply)
__global__ void init_agg_kernel(const float* __restrict__ h,
                                const float* __restrict__ eps, int l) {
    int i = blockIdx.x * blockDim.x + threadIdx.x;
    const int n4 = NNODES * DD / 4;
    if (i >= n4) return;
    float c = 1.f + __ldg(eps + l);
    float4 v = __ldg((const float4*)h + i);
    v.x *= c; v.y *= c; v.z *= c; v.w *= c;
    ((float4*)g_agg)[i] = v;
}

// message = relu(h[src] + bond embeddings); scatter-add into g_agg[dst]
__global__ void __launch_bounds__(256)
edge_kernel(const float* __restrict__ h,
            const int* __restrict__ src, const int* __restrict__ dst,
            const int* __restrict__ ea, const float* __restrict__ bond) {
    int warp  = (blockIdx.x * blockDim.x + threadIdx.x) >> 5;
    int lane  = threadIdx.x & 31;
    int nwarp = (gridDim.x * blockDim.x) >> 5;
    for (int e = warp; e < EDGES; e += nwarp) {
        int s  = __ldg(src + e);
        int d  = __ldg(dst + e);
        int a0 = __ldg(ea + 3 * e + 0);
        int a1 = __ldg(ea + 3 * e + 1);
        int a2 = __ldg(ea + 3 * e + 2);
        float4 v  = __ldg((const float4*)(h + (size_t)s * DD) + lane);
        float4 e0 = __ldg((const float4*)(bond + (size_t)(a0)      * DD) + lane);
        float4 e1 = __ldg((const float4*)(bond + (size_t)(5 + a1)  * DD) + lane);
        float4 e2 = __ldg((const float4*)(bond + (size_t)(11 + a2) * DD) + lane);
        v.x = fmaxf(v.x + e0.x + e1.x + e2.x, 0.f);
        v.y = fmaxf(v.y + e0.y + e1.y + e2.y, 0.f);
        v.z = fmaxf(v.z + e0.z + e1.z + e2.z, 0.f);
        v.w = fmaxf(v.w + e0.w + e1.w + e2.w, 0.f);
        red_add_v4(g_agg + (size_t)d * DD + lane * 4, v);
    }
}

// ---------------- 3xTF32 tensor-core GEMM ----------------
// C[M,NC] = act(A)[M,K] @ B[K,NC] + bias, act = BN1+ReLU when BNA.
// Each operand split hi/lo; acc += Ahi*Blo + Alo*Bhi + Ahi*Bhi (3 mmas).
// Block: 256 thr = 8 warps (4 m x 2 n), tile 128x128, warp tile 32x64, BK=16.
template<int K, int NC, bool BNA>
__global__ void __launch_bounds__(256)
gemm_tc_kernel(const float* __restrict__ A, const float* __restrict__ B,
               const float* __restrict__ bias, float* __restrict__ C, int M,
               const float* __restrict__ bsum, const float* __restrict__ bsq,
               const float* __restrict__ gam,  const float* __restrict__ bet) {
    constexpr int BM = 128, BN = 128, BK = 16;
    constexpr int KS = BNA ? K : 1;
    __shared__ uint32_t AsH[BK][BM + 4];
    __shared__ uint32_t AsL[BK][BM + 4];
    __shared__ uint32_t BsH[BK][BN + 4];
    __shared__ uint32_t BsL[BK][BN + 4];
    __shared__ float ssc[KS], ssh[KS];

    int tid = threadIdx.x;
    if (BNA) {
        float invM = 1.f / (float)M;
        for (int k = tid; k < K; k += 256) {
            float mu  = bsum[k] * invM;
            float var = bsq[k] * invM - mu * mu;
            float s   = gam[k] * rsqrtf(var + 1e-5f);
            ssc[k] = s;
            ssh[k] = bet[k] - mu * s;
        }
        __syncthreads();
    }

    int bm = blockIdx.x * BM;
    int bn = blockIdx.y * BN;
    int lane = tid & 31;
    int warp = tid >> 5;
    int wm = (warp & 3) * 32;
    int wn = (warp >> 2) * 64;
    int g = lane >> 2;
    int t = lane & 3;

    float acc[2][8][4];
#pragma unroll
    for (int mi = 0; mi < 2; ++mi)
#pragma unroll
        for (int ni = 0; ni < 8; ++ni)
#pragma unroll
            for (int j = 0; j < 4; ++j) acc[mi][ni][j] = 0.f;

    float4 pa[2], pb[2];

    // prefetch tile 0
#pragma unroll
    for (int it = 0; it < 2; ++it) {
        int f4 = tid * 2 + it, r = f4 >> 2, c4 = f4 & 3;
        int gr = bm + r;
        pa[it] = (gr < M) ? __ldg((const float4*)(A + (size_t)gr * K + c4 * 4))
                          : make_float4(0.f, 0.f, 0.f, 0.f);
        int rB = f4 >> 5, cB = (f4 & 31) * 4;
        pb[it] = __ldg((const float4*)(B + (size_t)rB * NC + bn + cB));
    }

    for (int k0 = 0; k0 < K; k0 += BK) {
        // store prefetched regs -> smem (split hi/lo, A transposed)
#pragma unroll
        for (int it = 0; it < 2; ++it) {
            int f4 = tid * 2 + it, r = f4 >> 2, c4 = f4 & 3;
            float4 v = pa[it];
            if (BNA) {
                int kk = k0 + c4 * 4;
                v.x = fmaxf(fmaf(v.x, ssc[kk + 0], ssh[kk + 0]), 0.f);
                v.y = fmaxf(fmaf(v.y, ssc[kk + 1], ssh[kk + 1]), 0.f);
                v.z = fmaxf(fmaf(v.z, ssc[kk + 2], ssh[kk + 2]), 0.f);
                v.w = fmaxf(fmaf(v.w, ssc[kk + 3], ssh[kk + 3]), 0.f);
            }
            uint32_t h0, l0, h1, l1, h2, l2, h3, l3;
            tf_split(v.x, h0, l0); tf_split(v.y, h1, l1);
            tf_split(v.z, h2, l2); tf_split(v.w, h3, l3);
            AsH[c4 * 4 + 0][r] = h0; AsL[c4 * 4 + 0][r] = l0;
            AsH[c4 * 4 + 1][r] = h1; AsL[c4 * 4 + 1][r] = l1;
            AsH[c4 * 4 + 2][r] = h2; AsL[c4 * 4 + 2][r] = l2;
            AsH[c4 * 4 + 3][r] = h3; AsL[c4 * 4 + 3][r] = l3;

            int rB = f4 >> 5, cB = (f4 & 31) * 4;
            uint4 uh, ul;
            tf_split(pb[it].x, uh.x, ul.x); tf_split(pb[it].y, uh.y, ul.y);
            tf_split(pb[it].z, uh.z, ul.z); tf_split(pb[it].w, uh.w, ul.w);
            *(uint4*)&BsH[rB][cB] = uh;
            *(uint4*)&BsL[rB][cB] = ul;
        }
        __syncthreads();

        // prefetch next tile while computing
        if (k0 + BK < K) {
            int kn = k0 + BK;
#pragma unroll
            for (int it = 0; it < 2; ++it) {
                int f4 = tid * 2 + it, r = f4 >> 2, c4 = f4 & 3;
                int gr = bm + r;
                pa[it] = (gr < M)
                    ? __ldg((const float4*)(A + (size_t)gr * K + kn + c4 * 4))
                    : make_float4(0.f, 0.f, 0.f, 0.f);
                int rB = f4 >> 5, cB = (f4 & 31) * 4;
                pb[it] = __ldg((const float4*)(B + (size_t)(kn + rB) * NC + bn + cB));
            }
        }

        // compute: two k8 steps, 3 mmas per (mi,ni)
#pragma unroll
        for (int kk = 0; kk < BK; kk += 8) {
            uint32_t afh[2][4], afl[2][4];
#pragma unroll
            for (int mi = 0; mi < 2; ++mi) {
                int row = wm + mi * 16 + g;
                afh[mi][0] = AsH[kk + t][row];
                afh[mi][1] = AsH[kk + t][row + 8];
                afh[mi][2] = AsH[kk + t + 4][row];
                afh[mi][3] = AsH[kk + t + 4][row + 8];
                afl[mi][0] = AsL[kk + t][row];
                afl[mi][1] = AsL[kk + t][row + 8];
                afl[mi][2] = AsL[kk + t + 4][row];
                afl[mi][3] = AsL[kk + t + 4][row + 8];
            }
#pragma unroll
            for (int ni = 0; ni < 8; ++ni) {
                int col = wn + ni * 8 + g;
                uint32_t bh[2], bl[2];
                bh[0] = BsH[kk + t][col];
                bh[1] = BsH[kk + t + 4][col];
                bl[0] = BsL[kk + t][col];
                bl[1] = BsL[kk + t + 4][col];
#pragma unroll
                for (int mi = 0; mi < 2; ++mi) {
                    mma_tf32(acc[mi][ni], afh[mi], bl);
                    mma_tf32(acc[mi][ni], afl[mi], bh);
                    mma_tf32(acc[mi][ni], afh[mi], bh);
                }
            }
        }
        __syncthreads();
    }

    // epilogue: + bias, float2 stores
#pragma unroll
    for (int mi = 0; mi < 2; ++mi) {
        int row0 = bm + wm + mi * 16 + g;
        int row1 = row0 + 8;
#pragma unroll
        for (int ni = 0; ni < 8; ++ni) {
            int col = bn + wn + ni * 8 + 2 * t;
            float bx = __ldg(bias + col), by = __ldg(bias + col + 1);
            if (row0 < M) {
                float2 o0 = make_float2(acc[mi][ni][0] + bx, acc[mi][ni][1] + by);
                *(float2*)(C + (size_t)row0 * NC + col) = o0;
            }
            if (row1 < M) {
                float2 o1 = make_float2(acc[mi][ni][2] + bx, acc[mi][ni][3] + by);
                *(float2*)(C + (size_t)row1 * NC + col) = o1;
            }
        }
    }
}

// column sums / sum-of-squares of A[M,C]
template<int C>
__global__ void col_stats_kernel(const float* __restrict__ A, int M,
                                 float* __restrict__ sum, float* __restrict__ sq) {
    int t  = threadIdx.x;
    int r0 = blockIdx.x * 256;
    int re = min(r0 + 256, M);
    float s = 0.f, q = 0.f;
    for (int r = r0; r < re; ++r) {
        float v = __ldg(A + (size_t)r * C + t);
        s += v;
        q = fmaf(v, v, q);
    }
    atomicAdd(sum + t, s);
    atomicAdd(sq + t, q);
}

__global__ void bn2_finalize_kernel(const float* __restrict__ gam,
                                    const float* __restrict__ bet, float invM) {
    int t = threadIdx.x;
    if (t < DD) {
        float mu  = g_sum2[t] * invM;
        float var = g_sq2[t] * invM - mu * mu;
        float s   = __ldg(gam + t) * rsqrtf(var + 1e-5f);
        g_scale2[t] = s;
        g_shift2[t] = __ldg(bet + t) - mu * s;
    }
}

// out = bn2(z2) [+ relu]; optionally also write agg_next = (1+eps[lnext])*out
__global__ void bn2_apply_kernel(const float* __restrict__ z,
                                 float* __restrict__ out,
                                 float* __restrict__ agg_next,
                                 const float* __restrict__ eps, int lnext,
                                 int do_relu) {
    int i = blockIdx.x * blockDim.x + threadIdx.x;
    const int n4 = NNODES * DD / 4;
    if (i >= n4) return;
    int c = (i & (DD / 4 - 1)) << 2;
    float4 v = __ldg((const float4*)z + i);
    v.x = fmaf(v.x, g_scale2[c + 0], g_shift2[c + 0]);
    v.y = fmaf(v.y, g_scale2[c + 1], g_shift2[c + 1]);
    v.z = fmaf(v.z, g_scale2[c + 2], g_shift2[c + 2]);
    v.w = fmaf(v.w, g_scale2[c + 3], g_shift2[c + 3]);
    if (do_relu) {
        v.x = fmaxf(v.x, 0.f); v.y = fmaxf(v.y, 0.f);
        v.z = fmaxf(v.z, 0.f); v.w = fmaxf(v.w, 0.f);
    }
    ((float4*)out)[i] = v;
    if (agg_next) {
        float ce = 1.f + __ldg(eps + lnext);
        float4 a = make_float4(v.x * ce, v.y * ce, v.z * ce, v.w * ce);
        ((float4*)agg_next)[i] = a;
    }
}

// ---------------- host launcher ----------------
extern "C" void kernel_launch(void* const* d_in, const int* in_sizes, int n_in,
                              void* d_out, int out_size) {
    const float* x    = (const float*)d_in[0];
    const int*   ei   = (const int*)  d_in[1];
    const int*   ea   = (const int*)  d_in[2];
    const float* W1   = (const float*)d_in[3];
    const float* b1   = (const float*)d_in[4];
    const float* g1   = (const float*)d_in[5];
    const float* bb1  = (const float*)d_in[6];
    const float* W2   = (const float*)d_in[7];
    const float* b2   = (const float*)d_in[8];
    const float* eps  = (const float*)d_in[9];
    const float* bond = (const float*)d_in[10];
    const float* g2   = (const float*)d_in[11];
    const float* bb2  = (const float*)d_in[12];
    float* out = (float*)d_out;

    float *p_agg, *p_y, *p_z2, *p_h;
    float *p_sum1, *p_sq1, *p_sum2, *p_sq2;
    cudaGetSymbolAddress((void**)&p_agg,  g_agg);
    cudaGetSymbolAddress((void**)&p_y,    g_y);
    cudaGetSymbolAddress((void**)&p_z2,   g_z2);
    cudaGetSymbolAddress((void**)&p_h,    g_h);
    cudaGetSymbolAddress((void**)&p_sum1, g_sum1);
    cudaGetSymbolAddress((void**)&p_sq1,  g_sq1);
    cudaGetSymbolAddress((void**)&p_sum2, g_sum2);
    cudaGetSymbolAddress((void**)&p_sq2,  g_sq2);

    const int M = NNODES;
    const int ew_blocks = (NNODES * DD / 4 + 255) / 256;
    const int st_blocks = (M + 255) / 256;
    const dim3 g1grid((M + 127) / 128, HH / 128);   // 391 x 2
    const dim3 g2grid((M + 127) / 128, DD / 128);   // 391 x 1
    const float invM = 1.f / (float)M;

    const float* hcur = x;
    for (int l = 0; l < LL; ++l) {
        zero_stats_kernel<<<1, 256>>>();
        if (l == 0)
            init_agg_kernel<<<ew_blocks, 256>>>(hcur, eps, 0);
        edge_kernel<<<1024, 256>>>(hcur, ei, ei + EDGES, ea,
                                   bond + (size_t)l * BOND_ROWS * DD);
        // GEMM1 (3xTF32 TC): y = agg @ W1[l] + b1[l]
        gemm_tc_kernel<DD, HH, false><<<g1grid, 256>>>(
            p_agg, W1 + (size_t)l * DD * HH, b1 + (size_t)l * HH, p_y, M,
            nullptr, nullptr, nullptr, nullptr);
        col_stats_kernel<HH><<<st_blocks, HH>>>(p_y, M, p_sum1, p_sq1);
        // GEMM2 (3xTF32 TC, fused BN1+ReLU on A): z2 = act(y) @ W2[l] + b2[l]
        gemm_tc_kernel<HH, DD, true><<<g2grid, 256>>>(
            p_y, W2 + (size_t)l * HH * DD, b2 + (size_t)l * DD, p_z2, M,
            p_sum1, p_sq1, g1 + (size_t)l * HH, bb1 + (size_t)l * HH);
        col_stats_kernel<DD><<<st_blocks, DD>>>(p_z2, M, p_sum2, p_sq2);
        bn2_finalize_kernel<<<1, 128>>>(g2 + (size_t)l * DD,
                                        bb2 + (size_t)l * DD, invM);
        bool last = (l == LL - 1);
        bn2_apply_kernel<<<ew_blocks, 256>>>(
            p_z2, last ? out : p_h, last ? nullptr : p_agg, eps, l + 1,
            last ? 0 : 1);
        hcur = p_h;
    }
}

// round 5
// speedup vs baseline: 1.1891x; 1.1279x over previous
#include <cuda_runtime.h>
#include <cstdint>

#define NNODES 50000
#define EDGES  400000
#define DD     128
#define HH     256
#define LL     5
#define BOND_ROWS 13

// ---------------- scratch (device globals; no allocation) ----------------
__device__ float g_agg[(size_t)NNODES * DD];
__device__ float g_y  [(size_t)NNODES * HH];
__device__ float g_z2 [(size_t)NNODES * DD];
__device__ float g_h  [(size_t)NNODES * DD];
__device__ float g_sum1[HH], g_sq1[HH];
__device__ float g_sum2[DD], g_sq2[DD];
__device__ float g_scale2[DD], g_shift2[DD];

// ---------------- helpers ----------------
__device__ __forceinline__ void red_add_v4(float* addr, float4 v) {
    asm volatile("red.global.add.v4.f32 [%0], {%1,%2,%3,%4};"
                 :: "l"(addr), "f"(v.x), "f"(v.y), "f"(v.z), "f"(v.w)
                 : "memory");
}
__device__ __forceinline__ uint32_t f2tf(float f) {
    uint32_t u;
    asm("cvt.rna.tf32.f32 %0, %1;" : "=r"(u) : "f"(f));
    return u;
}
__device__ __forceinline__ void tf_split(float a, uint32_t& hi, uint32_t& lo) {
    hi = f2tf(a);
    lo = f2tf(a - __uint_as_float(hi));
}
__device__ __forceinline__ void mma_tf32(float* c, const uint32_t* a, const uint32_t* b) {
    asm volatile(
        "mma.sync.aligned.m16n8k8.row.col.f32.tf32.tf32.f32 "
        "{%0,%1,%2,%3}, {%4,%5,%6,%7}, {%8,%9}, {%0,%1,%2,%3};"
        : "+f"(c[0]), "+f"(c[1]), "+f"(c[2]), "+f"(c[3])
        : "r"(a[0]), "r"(a[1]), "r"(a[2]), "r"(a[3]), "r"(b[0]), "r"(b[1]));
}

// ---------------- small kernels ----------------
__global__ void zero_stats_kernel() {
    int t = threadIdx.x;
    if (t < HH) { g_sum1[t] = 0.f; g_sq1[t] = 0.f; }
    if (t < DD) { g_sum2[t] = 0.f; g_sq2[t] = 0.f; }
}

// agg = (1 + eps[0]) * x   (layer 0 only; later layers fused into bn2_apply)
__global__ void init_agg_kernel(const float* __restrict__ h,
                                const float* __restrict__ eps, int l) {
    int i = blockIdx.x * blockDim.x + threadIdx.x;
    const int n4 = NNODES * DD / 4;
    if (i >= n4) return;
    float c = 1.f + __ldg(eps + l);
    float4 v = __ldg((const float4*)h + i);
    v.x *= c; v.y *= c; v.z *= c; v.w *= c;
    ((float4*)g_agg)[i] = v;
}

// message = relu(h[src] + bond embeddings); scatter-add into g_agg[dst]
__global__ void __launch_bounds__(256)
edge_kernel(const float* __restrict__ h,
            const int* __restrict__ src, const int* __restrict__ dst,
            const int* __restrict__ ea, const float* __restrict__ bond) {
    int warp  = (blockIdx.x * blockDim.x + threadIdx.x) >> 5;
    int lane  = threadIdx.x & 31;
    int nwarp = (gridDim.x * blockDim.x) >> 5;
    for (int e = warp; e < EDGES; e += nwarp) {
        int s  = __ldg(src + e);
        int d  = __ldg(dst + e);
        int a0 = __ldg(ea + 3 * e + 0);
        int a1 = __ldg(ea + 3 * e + 1);
        int a2 = __ldg(ea + 3 * e + 2);
        float4 v  = __ldg((const float4*)(h + (size_t)s * DD) + lane);
        float4 e0 = __ldg((const float4*)(bond + (size_t)(a0)      * DD) + lane);
        float4 e1 = __ldg((const float4*)(bond + (size_t)(5 + a1)  * DD) + lane);
        float4 e2 = __ldg((const float4*)(bond + (size_t)(11 + a2) * DD) + lane);
        v.x = fmaxf(v.x + e0.x + e1.x + e2.x, 0.f);
        v.y = fmaxf(v.y + e0.y + e1.y + e2.y, 0.f);
        v.z = fmaxf(v.z + e0.z + e1.z + e2.z, 0.f);
        v.w = fmaxf(v.w + e0.w + e1.w + e2.w, 0.f);
        red_add_v4(g_agg + (size_t)d * DD + lane * 4, v);
    }
}

// ---------------- 3xTF32 tensor-core GEMM + fused column stats ----------------
// C[M,NC] = act(A)[M,K] @ B[K,NC] + bias, act = BN1+ReLU when BNA.
// Epilogue also accumulates per-column sum / sum-of-squares of C into
// osum/osq via warp-reduced atomics (replaces separate col_stats pass).
template<int K, int NC, bool BNA>
__global__ void __launch_bounds__(256, 2)
gemm_tc_kernel(const float* __restrict__ A, const float* __restrict__ B,
               const float* __restrict__ bias, float* __restrict__ C, int M,
               const float* __restrict__ bsum, const float* __restrict__ bsq,
               const float* __restrict__ gam,  const float* __restrict__ bet,
               float* __restrict__ osum, float* __restrict__ osq) {
    constexpr int BM = 128, BN = 128, BK = 16;
    constexpr int KS = BNA ? K : 1;
    __shared__ uint32_t AsH[BK][BM + 4];
    __shared__ uint32_t AsL[BK][BM + 4];
    __shared__ uint32_t BsH[BK][BN + 4];
    __shared__ uint32_t BsL[BK][BN + 4];
    __shared__ float ssc[KS], ssh[KS];

    int tid = threadIdx.x;
    if (BNA) {
        float invM = 1.f / (float)M;
        for (int k = tid; k < K; k += 256) {
            float mu  = bsum[k] * invM;
            float var = bsq[k] * invM - mu * mu;
            float s   = gam[k] * rsqrtf(var + 1e-5f);
            ssc[k] = s;
            ssh[k] = bet[k] - mu * s;
        }
        __syncthreads();
    }

    int bm = blockIdx.x * BM;
    int bn = blockIdx.y * BN;
    int lane = tid & 31;
    int warp = tid >> 5;
    int wm = (warp & 3) * 32;
    int wn = (warp >> 2) * 64;
    int g = lane >> 2;
    int t = lane & 3;

    float acc[2][8][4];
#pragma unroll
    for (int mi = 0; mi < 2; ++mi)
#pragma unroll
        for (int ni = 0; ni < 8; ++ni)
#pragma unroll
            for (int j = 0; j < 4; ++j) acc[mi][ni][j] = 0.f;

    float4 pa[2], pb[2];

    // prefetch tile 0
#pragma unroll
    for (int it = 0; it < 2; ++it) {
        int f4 = tid * 2 + it, r = f4 >> 2, c4 = f4 & 3;
        int gr = bm + r;
        pa[it] = (gr < M) ? __ldg((const float4*)(A + (size_t)gr * K + c4 * 4))
                          : make_float4(0.f, 0.f, 0.f, 0.f);
        int rB = f4 >> 5, cB = (f4 & 31) * 4;
        pb[it] = __ldg((const float4*)(B + (size_t)rB * NC + bn + cB));
    }

    for (int k0 = 0; k0 < K; k0 += BK) {
        // store prefetched regs -> smem (split hi/lo, A transposed)
#pragma unroll
        for (int it = 0; it < 2; ++it) {
            int f4 = tid * 2 + it, r = f4 >> 2, c4 = f4 & 3;
            float4 v = pa[it];
            if (BNA) {
                int kk = k0 + c4 * 4;
                v.x = fmaxf(fmaf(v.x, ssc[kk + 0], ssh[kk + 0]), 0.f);
                v.y = fmaxf(fmaf(v.y, ssc[kk + 1], ssh[kk + 1]), 0.f);
                v.z = fmaxf(fmaf(v.z, ssc[kk + 2], ssh[kk + 2]), 0.f);
                v.w = fmaxf(fmaf(v.w, ssc[kk + 3], ssh[kk + 3]), 0.f);
            }
            uint32_t h0, l0, h1, l1, h2, l2, h3, l3;
            tf_split(v.x, h0, l0); tf_split(v.y, h1, l1);
            tf_split(v.z, h2, l2); tf_split(v.w, h3, l3);
            AsH[c4 * 4 + 0][r] = h0; AsL[c4 * 4 + 0][r] = l0;
            AsH[c4 * 4 + 1][r] = h1; AsL[c4 * 4 + 1][r] = l1;
            AsH[c4 * 4 + 2][r] = h2; AsL[c4 * 4 + 2][r] = l2;
            AsH[c4 * 4 + 3][r] = h3; AsL[c4 * 4 + 3][r] = l3;

            int rB = f4 >> 5, cB = (f4 & 31) * 4;
            uint4 uh, ul;
            tf_split(pb[it].x, uh.x, ul.x); tf_split(pb[it].y, uh.y, ul.y);
            tf_split(pb[it].z, uh.z, ul.z); tf_split(pb[it].w, uh.w, ul.w);
            *(uint4*)&BsH[rB][cB] = uh;
            *(uint4*)&BsL[rB][cB] = ul;
        }
        __syncthreads();

        // prefetch next tile while computing
        if (k0 + BK < K) {
            int kn = k0 + BK;
#pragma unroll
            for (int it = 0; it < 2; ++it) {
                int f4 = tid * 2 + it, r = f4 >> 2, c4 = f4 & 3;
                int gr = bm + r;
                pa[it] = (gr < M)
                    ? __ldg((const float4*)(A + (size_t)gr * K + kn + c4 * 4))
                    : make_float4(0.f, 0.f, 0.f, 0.f);
                int rB = f4 >> 5, cB = (f4 & 31) * 4;
                pb[it] = __ldg((const float4*)(B + (size_t)(kn + rB) * NC + bn + cB));
            }
        }

        // compute: two k8 steps, 3 mmas per (mi,ni)
#pragma unroll
        for (int kk = 0; kk < BK; kk += 8) {
            uint32_t afh[2][4], afl[2][4];
#pragma unroll
            for (int mi = 0; mi < 2; ++mi) {
                int row = wm + mi * 16 + g;
                afh[mi][0] = AsH[kk + t][row];
                afh[mi][1] = AsH[kk + t][row + 8];
                afh[mi][2] = AsH[kk + t + 4][row];
                afh[mi][3] = AsH[kk + t + 4][row + 8];
                afl[mi][0] = AsL[kk + t][row];
                afl[mi][1] = AsL[kk + t][row + 8];
                afl[mi][2] = AsL[kk + t + 4][row];
                afl[mi][3] = AsL[kk + t + 4][row + 8];
            }
#pragma unroll
            for (int ni = 0; ni < 8; ++ni) {
                int col = wn + ni * 8 + g;
                uint32_t bh[2], bl[2];
                bh[0] = BsH[kk + t][col];
                bh[1] = BsH[kk + t + 4][col];
                bl[0] = BsL[kk + t][col];
                bl[1] = BsL[kk + t + 4][col];
#pragma unroll
                for (int mi = 0; mi < 2; ++mi) {
                    mma_tf32(acc[mi][ni], afh[mi], bl);
                    mma_tf32(acc[mi][ni], afl[mi], bh);
                    mma_tf32(acc[mi][ni], afh[mi], bh);
                }
            }
        }
        __syncthreads();
    }

    // epilogue: + bias, store, and fused per-column stats
#pragma unroll
    for (int ni = 0; ni < 8; ++ni) {
        int col = bn + wn + ni * 8 + 2 * t;
        float bx = __ldg(bias + col), by = __ldg(bias + col + 1);
        float s0 = 0.f, q0 = 0.f, s1 = 0.f, q1 = 0.f;
#pragma unroll
        for (int mi = 0; mi < 2; ++mi) {
            int row0 = bm + wm + mi * 16 + g;
            int row1 = row0 + 8;
            if (row0 < M) {
                float v0 = acc[mi][ni][0] + bx;
                float v1 = acc[mi][ni][1] + by;
                *(float2*)(C + (size_t)row0 * NC + col) = make_float2(v0, v1);
                s0 += v0; q0 = fmaf(v0, v0, q0);
                s1 += v1; q1 = fmaf(v1, v1, q1);
            }
            if (row1 < M) {
                float v2 = acc[mi][ni][2] + bx;
                float v3 = acc[mi][ni][3] + by;
                *(float2*)(C + (size_t)row1 * NC + col) = make_float2(v2, v3);
                s0 += v2; q0 = fmaf(v2, v2, q0);
                s1 += v3; q1 = fmaf(v3, v3, q1);
            }
        }
        // reduce over g (lane bits 2..4); t is preserved by xor 4/8/16
#pragma unroll
        for (int o = 4; o < 32; o <<= 1) {
            s0 += __shfl_xor_sync(0xFFFFFFFF, s0, o);
            q0 += __shfl_xor_sync(0xFFFFFFFF, q0, o);
            s1 += __shfl_xor_sync(0xFFFFFFFF, s1, o);
            q1 += __shfl_xor_sync(0xFFFFFFFF, q1, o);
        }
        if (g == 0) {
            atomicAdd(osum + col,     s0);
            atomicAdd(osq  + col,     q0);
            atomicAdd(osum + col + 1, s1);
            atomicAdd(osq  + col + 1, q1);
        }
    }
}

__global__ void bn2_finalize_kernel(const float* __restrict__ gam,
                                    const float* __restrict__ bet, float invM) {
    int t = threadIdx.x;
    if (t < DD) {
        float mu  = g_sum2[t] * invM;
        float var = g_sq2[t] * invM - mu * mu;
        float s   = __ldg(gam + t) * rsqrtf(var + 1e-5f);
        g_scale2[t] = s;
        g_shift2[t] = __ldg(bet + t) - mu * s;
    }
}

// out = bn2(z2) [+ relu]; optionally also write agg_next = (1+eps[lnext])*out
__global__ void bn2_apply_kernel(const float* __restrict__ z,
                                 float* __restrict__ out,
                                 float* __restrict__ agg_next,
                                 const float* __restrict__ eps, int lnext,
                                 int do_relu) {
    int i = blockIdx.x * blockDim.x + threadIdx.x;
    const int n4 = NNODES * DD / 4;
    if (i >= n4) return;
    int c = (i & (DD / 4 - 1)) << 2;
    float4 v = __ldg((const float4*)z + i);
    v.x = fmaf(v.x, g_scale2[c + 0], g_shift2[c + 0]);
    v.y = fmaf(v.y, g_scale2[c + 1], g_shift2[c + 1]);
    v.z = fmaf(v.z, g_scale2[c + 2], g_shift2[c + 2]);
    v.w = fmaf(v.w, g_scale2[c + 3], g_shift2[c + 3]);
    if (do_relu) {
        v.x = fmaxf(v.x, 0.f); v.y = fmaxf(v.y, 0.f);
        v.z = fmaxf(v.z, 0.f); v.w = fmaxf(v.w, 0.f);
    }
    ((float4*)out)[i] = v;
    if (agg_next) {
        float ce = 1.f + __ldg(eps + lnext);
        float4 a = make_float4(v.x * ce, v.y * ce, v.z * ce, v.w * ce);
        ((float4*)agg_next)[i] = a;
    }
}

// ---------------- host launcher ----------------
extern "C" void kernel_launch(void* const* d_in, const int* in_sizes, int n_in,
                              void* d_out, int out_size) {
    const float* x    = (const float*)d_in[0];
    const int*   ei   = (const int*)  d_in[1];
    const int*   ea   = (const int*)  d_in[2];
    const float* W1   = (const float*)d_in[3];
    const float* b1   = (const float*)d_in[4];
    const float* g1   = (const float*)d_in[5];
    const float* bb1  = (const float*)d_in[6];
    const float* W2   = (const float*)d_in[7];
    const float* b2   = (const float*)d_in[8];
    const float* eps  = (const float*)d_in[9];
    const float* bond = (const float*)d_in[10];
    const float* g2   = (const float*)d_in[11];
    const float* bb2  = (const float*)d_in[12];
    float* out = (float*)d_out;

    float *p_agg, *p_y, *p_z2, *p_h;
    float *p_sum1, *p_sq1, *p_sum2, *p_sq2;
    cudaGetSymbolAddress((void**)&p_agg,  g_agg);
    cudaGetSymbolAddress((void**)&p_y,    g_y);
    cudaGetSymbolAddress((void**)&p_z2,   g_z2);
    cudaGetSymbolAddress((void**)&p_h,    g_h);
    cudaGetSymbolAddress((void**)&p_sum1, g_sum1);
    cudaGetSymbolAddress((void**)&p_sq1,  g_sq1);
    cudaGetSymbolAddress((void**)&p_sum2, g_sum2);
    cudaGetSymbolAddress((void**)&p_sq2,  g_sq2);

    const int M = NNODES;
    const int ew_blocks = (NNODES * DD / 4 + 255) / 256;
    const dim3 g1grid((M + 127) / 128, HH / 128);   // 391 x 2
    const dim3 g2grid((M + 127) / 128, DD / 128);   // 391 x 1
    const float invM = 1.f / (float)M;

    const float* hcur = x;
    for (int l = 0; l < LL; ++l) {
        zero_stats_kernel<<<1, 256>>>();
        if (l == 0)
            init_agg_kernel<<<ew_blocks, 256>>>(hcur, eps, 0);
        edge_kernel<<<1024, 256>>>(hcur, ei, ei + EDGES, ea,
                                   bond + (size_t)l * BOND_ROWS * DD);
        // GEMM1 (3xTF32 TC, fused BN1 stats): y = agg @ W1[l] + b1[l]
        gemm_tc_kernel<DD, HH, false><<<g1grid, 256>>>(
            p_agg, W1 + (size_t)l * DD * HH, b1 + (size_t)l * HH, p_y, M,
            nullptr, nullptr, nullptr, nullptr, p_sum1, p_sq1);
        // GEMM2 (3xTF32 TC, fused BN1+ReLU on A, fused BN2 stats)
        gemm_tc_kernel<HH, DD, true><<<g2grid, 256>>>(
            p_y, W2 + (size_t)l * HH * DD, b2 + (size_t)l * DD, p_z2, M,
            p_sum1, p_sq1, g1 + (size_t)l * HH, bb1 + (size_t)l * HH,
            p_sum2, p_sq2);
        bn2_finalize_kernel<<<1, 128>>>(g2 + (size_t)l * DD,
                                        bb2 + (size_t)l * DD, invM);
        bool last = (l == LL - 1);
        bn2_apply_kernel<<<ew_blocks, 256>>>(
            p_z2, last ? out : p_h, last ? nullptr : p_agg, eps, l + 1,
            last ? 0 : 1);
        hcur = p_h;
    }
}

// round 6
// speedup vs baseline: 1.2290x; 1.0336x over previous
#include <cuda_runtime.h>
#include <cuda_bf16.h>
#include <cstdint>

#define NNODES 50000
#define EDGES  400000
#define DD     128
#define HH     256
#define LL     5
#define BOND_ROWS 13

// ---------------- scratch (device globals; no allocation) ----------------
__device__ float g_agg[(size_t)NNODES * DD];
__device__ float g_y  [(size_t)NNODES * HH];
__device__ float g_z2 [(size_t)NNODES * DD];
__device__ float g_h  [(size_t)NNODES * DD];
__device__ float g_sum1[HH], g_sq1[HH];
__device__ float g_sum2[DD], g_sq2[DD];
__device__ float g_scale2[DD], g_shift2[DD];

// ---------------- helpers ----------------
__device__ __forceinline__ void red_add_v4(float* addr, float4 v) {
    asm volatile("red.global.add.v4.f32 [%0], {%1,%2,%3,%4};"
                 :: "l"(addr), "f"(v.x), "f"(v.y), "f"(v.z), "f"(v.w)
                 : "memory");
}
// round to bf16 and back
__device__ __forceinline__ float bfr(float a) {
    return __bfloat162float(__float2bfloat16_rn(a));
}
// pack two floats as bf16x2: low half = e0 (even k), high half = e1 (odd k)
__device__ __forceinline__ uint32_t packbf(float e0, float e1) {
    uint32_t r;
    asm("cvt.rn.bf16x2.f32 %0, %1, %2;" : "=r"(r) : "f"(e1), "f"(e0));
    return r;
}
__device__ __forceinline__ void mma_bf16(float* c, const uint32_t* a, const uint32_t* b) {
    asm volatile(
        "mma.sync.aligned.m16n8k16.row.col.f32.bf16.bf16.f32 "
        "{%0,%1,%2,%3}, {%4,%5,%6,%7}, {%8,%9}, {%0,%1,%2,%3};"
        : "+f"(c[0]), "+f"(c[1]), "+f"(c[2]), "+f"(c[3])
        : "r"(a[0]), "r"(a[1]), "r"(a[2]), "r"(a[3]), "r"(b[0]), "r"(b[1]));
}

// ---------------- small kernels ----------------
__global__ void zero_stats_kernel() {
    int t = threadIdx.x;
    if (t < HH) { g_sum1[t] = 0.f; g_sq1[t] = 0.f; }
    if (t < DD) { g_sum2[t] = 0.f; g_sq2[t] = 0.f; }
}

__global__ void init_agg_kernel(const float* __restrict__ h,
                                const float* __restrict__ eps, int l) {
    int i = blockIdx.x * blockDim.x + threadIdx.x;
    const int n4 = NNODES * DD / 4;
    if (i >= n4) return;
    float c = 1.f + __ldg(eps + l);
    float4 v = __ldg((const float4*)h + i);
    v.x *= c; v.y *= c; v.z *= c; v.w *= c;
    ((float4*)g_agg)[i] = v;
}

// message = relu(h[src] + bond embeddings); scatter-add into g_agg[dst]
__global__ void __launch_bounds__(256)
edge_kernel(const float* __restrict__ h,
            const int* __restrict__ src, const int* __restrict__ dst,
            const int* __restrict__ ea, const float* __restrict__ bond) {
    int warp  = (blockIdx.x * blockDim.x + threadIdx.x) >> 5;
    int lane  = threadIdx.x & 31;
    int nwarp = (gridDim.x * blockDim.x) >> 5;
    for (int e = warp; e < EDGES; e += nwarp) {
        int s  = __ldg(src + e);
        int d  = __ldg(dst + e);
        int a0 = __ldg(ea + 3 * e + 0);
        int a1 = __ldg(ea + 3 * e + 1);
        int a2 = __ldg(ea + 3 * e + 2);
        float4 v  = __ldg((const float4*)(h + (size_t)s * DD) + lane);
        float4 e0 = __ldg((const float4*)(bond + (size_t)(a0)      * DD) + lane);
        float4 e1 = __ldg((const float4*)(bond + (size_t)(5 + a1)  * DD) + lane);
        float4 e2 = __ldg((const float4*)(bond + (size_t)(11 + a2) * DD) + lane);
        v.x = fmaxf(v.x + e0.x + e1.x + e2.x, 0.f);
        v.y = fmaxf(v.y + e0.y + e1.y + e2.y, 0.f);
        v.z = fmaxf(v.z + e0.z + e1.z + e2.z, 0.f);
        v.w = fmaxf(v.w + e0.w + e1.w + e2.w, 0.f);
        red_add_v4(g_agg + (size_t)d * DD + lane * 4, v);
    }
}

// ---------------- 3x-bf16 split tensor-core GEMM + fused column stats -------
// C[M,NC] = act(A)[M,K] @ B[K,NC] + bias, act = BN1+ReLU when BNA.
// Split a = hi + lo (bf16 each); acc += ah*bl + al*bh + ah*bh (3 mmas, k16).
// Epilogue accumulates per-column sum / sumsq of C into osum/osq.
template<int K, int NC, bool BNA>
__global__ void __launch_bounds__(256, 2)
gemm_tc_kernel(const float* __restrict__ A, const float* __restrict__ B,
               const float* __restrict__ bias, float* __restrict__ C, int M,
               const float* __restrict__ bsum, const float* __restrict__ bsq,
               const float* __restrict__ gam,  const float* __restrict__ bet,
               float* __restrict__ osum, float* __restrict__ osq) {
    constexpr int BM = 128, BN = 128, BK = 16, K2 = BK / 2;
    constexpr int KS = BNA ? K : 1;
    // pad 8: row stride 136 == 8 (mod 32) banks -> conflict-free frag loads
    __shared__ uint32_t AsH[K2][BM + 8];
    __shared__ uint32_t AsL[K2][BM + 8];
    __shared__ uint32_t BsH[K2][BN + 8];
    __shared__ uint32_t BsL[K2][BN + 8];
    __shared__ float ssc[KS], ssh[KS];

    int tid = threadIdx.x;
    if (BNA) {
        float invM = 1.f / (float)M;
        for (int k = tid; k < K; k += 256) {
            float mu  = bsum[k] * invM;
            float var = bsq[k] * invM - mu * mu;
            float s   = gam[k] * rsqrtf(var + 1e-5f);
            ssc[k] = s;
            ssh[k] = bet[k] - mu * s;
        }
        __syncthreads();
    }

    int bm = blockIdx.x * BM;
    int bn = blockIdx.y * BN;
    int lane = tid & 31;
    int warp = tid >> 5;
    int wm = (warp & 3) * 32;
    int wn = (warp >> 2) * 64;
    int g = lane >> 2;
    int t = lane & 3;

    float acc[2][8][4];
#pragma unroll
    for (int mi = 0; mi < 2; ++mi)
#pragma unroll
        for (int ni = 0; ni < 8; ++ni)
#pragma unroll
            for (int j = 0; j < 4; ++j) acc[mi][ni][j] = 0.f;

    // A loads: f4 = tid*2+it -> row r=f4>>2, k-group c4=f4&3 (4 floats)
    // B loads: k2r = tid>>5 (0..7), cg = tid&31 (float4 col group); two rows.
    const int k2r = tid >> 5;
    const int cg  = tid & 31;

    float4 pa[2], pb0, pb1;

    // prefetch tile 0
#pragma unroll
    for (int it = 0; it < 2; ++it) {
        int f4 = tid * 2 + it, r = f4 >> 2, c4 = f4 & 3;
        int gr = bm + r;
        pa[it] = (gr < M) ? __ldg((const float4*)(A + (size_t)gr * K + c4 * 4))
                          : make_float4(0.f, 0.f, 0.f, 0.f);
    }
    pb0 = __ldg((const float4*)(B + (size_t)(2 * k2r)     * NC + bn + cg * 4));
    pb1 = __ldg((const float4*)(B + (size_t)(2 * k2r + 1) * NC + bn + cg * 4));

    for (int k0 = 0; k0 < K; k0 += BK) {
        // ---- store prefetched regs -> smem (bf16 split, A transposed) ----
#pragma unroll
        for (int it = 0; it < 2; ++it) {
            int f4 = tid * 2 + it, r = f4 >> 2, c4 = f4 & 3;
            float4 v = pa[it];
            if (BNA) {
                int kk = k0 + c4 * 4;
                v.x = fmaxf(fmaf(v.x, ssc[kk + 0], ssh[kk + 0]), 0.f);
                v.y = fmaxf(fmaf(v.y, ssc[kk + 1], ssh[kk + 1]), 0.f);
                v.z = fmaxf(fmaf(v.z, ssc[kk + 2], ssh[kk + 2]), 0.f);
                v.w = fmaxf(fmaf(v.w, ssc[kk + 3], ssh[kk + 3]), 0.f);
            }
            float h0 = bfr(v.x), h1 = bfr(v.y), h2 = bfr(v.z), h3 = bfr(v.w);
            AsH[c4 * 2 + 0][r] = packbf(h0, h1);
            AsH[c4 * 2 + 1][r] = packbf(h2, h3);
            AsL[c4 * 2 + 0][r] = packbf(v.x - h0, v.y - h1);
            AsL[c4 * 2 + 1][r] = packbf(v.z - h2, v.w - h3);
        }
        {
            float bh0 = bfr(pb0.x), bh1 = bfr(pb0.y), bh2 = bfr(pb0.z), bh3 = bfr(pb0.w);
            float ch0 = bfr(pb1.x), ch1 = bfr(pb1.y), ch2 = bfr(pb1.z), ch3 = bfr(pb1.w);
            uint4 uh, ul;
            uh.x = packbf(bh0, ch0); uh.y = packbf(bh1, ch1);
            uh.z = packbf(bh2, ch2); uh.w = packbf(bh3, ch3);
            ul.x = packbf(pb0.x - bh0, pb1.x - ch0);
            ul.y = packbf(pb0.y - bh1, pb1.y - ch1);
            ul.z = packbf(pb0.z - bh2, pb1.z - ch2);
            ul.w = packbf(pb0.w - bh3, pb1.w - ch3);
            *(uint4*)&BsH[k2r][cg * 4] = uh;
            *(uint4*)&BsL[k2r][cg * 4] = ul;
        }
        __syncthreads();

        // ---- prefetch next tile ----
        if (k0 + BK < K) {
            int kn = k0 + BK;
#pragma unroll
            for (int it = 0; it < 2; ++it) {
                int f4 = tid * 2 + it, r = f4 >> 2, c4 = f4 & 3;
                int gr = bm + r;
                pa[it] = (gr < M)
                    ? __ldg((const float4*)(A + (size_t)gr * K + kn + c4 * 4))
                    : make_float4(0.f, 0.f, 0.f, 0.f);
            }
            pb0 = __ldg((const float4*)(B + (size_t)(kn + 2 * k2r)     * NC + bn + cg * 4));
            pb1 = __ldg((const float4*)(B + (size_t)(kn + 2 * k2r + 1) * NC + bn + cg * 4));
        }

        // ---- compute: one k16 step, 3 mmas per (mi,ni) ----
        {
            uint32_t ah[2][4], al[2][4];
#pragma unroll
            for (int mi = 0; mi < 2; ++mi) {
                int row = wm + mi * 16 + g;
                ah[mi][0] = AsH[t][row];     ah[mi][1] = AsH[t][row + 8];
                ah[mi][2] = AsH[t + 4][row]; ah[mi][3] = AsH[t + 4][row + 8];
                al[mi][0] = AsL[t][row];     al[mi][1] = AsL[t][row + 8];
                al[mi][2] = AsL[t + 4][row]; al[mi][3] = AsL[t + 4][row + 8];
            }
#pragma unroll
            for (int ni = 0; ni < 8; ++ni) {
                int col = wn + ni * 8 + g;
                uint32_t bh[2], bl[2];
                bh[0] = BsH[t][col]; bh[1] = BsH[t + 4][col];
                bl[0] = BsL[t][col]; bl[1] = BsL[t + 4][col];
#pragma unroll
                for (int mi = 0; mi < 2; ++mi) {
                    mma_bf16(acc[mi][ni], ah[mi], bl);
                    mma_bf16(acc[mi][ni], al[mi], bh);
                    mma_bf16(acc[mi][ni], ah[mi], bh);
                }
            }
        }
        __syncthreads();
    }

    // ---- epilogue: + bias, store, fused per-column stats ----
#pragma unroll
    for (int ni = 0; ni < 8; ++ni) {
        int col = bn + wn + ni * 8 + 2 * t;
        float bx = __ldg(bias + col), by = __ldg(bias + col + 1);
        float s0 = 0.f, q0 = 0.f, s1 = 0.f, q1 = 0.f;
#pragma unroll
        for (int mi = 0; mi < 2; ++mi) {
            int row0 = bm + wm + mi * 16 + g;
            int row1 = row0 + 8;
            if (row0 < M) {
                float v0 = acc[mi][ni][0] + bx;
                float v1 = acc[mi][ni][1] + by;
                *(float2*)(C + (size_t)row0 * NC + col) = make_float2(v0, v1);
                s0 += v0; q0 = fmaf(v0, v0, q0);
                s1 += v1; q1 = fmaf(v1, v1, q1);
            }
            if (row1 < M) {
                float v2 = acc[mi][ni][2] + bx;
                float v3 = acc[mi][ni][3] + by;
                *(float2*)(C + (size_t)row1 * NC + col) = make_float2(v2, v3);
                s0 += v2; q0 = fmaf(v2, v2, q0);
                s1 += v3; q1 = fmaf(v3, v3, q1);
            }
        }
#pragma unroll
        for (int o = 4; o < 32; o <<= 1) {
            s0 += __shfl_xor_sync(0xFFFFFFFF, s0, o);
            q0 += __shfl_xor_sync(0xFFFFFFFF, q0, o);
            s1 += __shfl_xor_sync(0xFFFFFFFF, s1, o);
            q1 += __shfl_xor_sync(0xFFFFFFFF, q1, o);
        }
        if (g == 0) {
            atomicAdd(osum + col,     s0);
            atomicAdd(osq  + col,     q0);
            atomicAdd(osum + col + 1, s1);
            atomicAdd(osq  + col + 1, q1);
        }
    }
}

__global__ void bn2_finalize_kernel(const float* __restrict__ gam,
                                    const float* __restrict__ bet, float invM) {
    int t = threadIdx.x;
    if (t < DD) {
        float mu  = g_sum2[t] * invM;
        float var = g_sq2[t] * invM - mu * mu;
        float s   = __ldg(gam + t) * rsqrtf(var + 1e-5f);
        g_scale2[t] = s;
        g_shift2[t] = __ldg(bet + t) - mu * s;
    }
}

__global__ void bn2_apply_kernel(const float* __restrict__ z,
                                 float* __restrict__ out,
                                 float* __restrict__ agg_next,
                                 const float* __restrict__ eps, int lnext,
                                 int do_relu) {
    int i = blockIdx.x * blockDim.x + threadIdx.x;
    const int n4 = NNODES * DD / 4;
    if (i >= n4) return;
    int c = (i & (DD / 4 - 1)) << 2;
    float4 v = __ldg((const float4*)z + i);
    v.x = fmaf(v.x, g_scale2[c + 0], g_shift2[c + 0]);
    v.y = fmaf(v.y, g_scale2[c + 1], g_shift2[c + 1]);
    v.z = fmaf(v.z, g_scale2[c + 2], g_shift2[c + 2]);
    v.w = fmaf(v.w, g_scale2[c + 3], g_shift2[c + 3]);
    if (do_relu) {
        v.x = fmaxf(v.x, 0.f); v.y = fmaxf(v.y, 0.f);
        v.z = fmaxf(v.z, 0.f); v.w = fmaxf(v.w, 0.f);
    }
    ((float4*)out)[i] = v;
    if (agg_next) {
        float ce = 1.f + __ldg(eps + lnext);
        float4 a = make_float4(v.x * ce, v.y * ce, v.z * ce, v.w * ce);
        ((float4*)agg_next)[i] = a;
    }
}

// ---------------- host launcher ----------------
extern "C" void kernel_launch(void* const* d_in, const int* in_sizes, int n_in,
                              void* d_out, int out_size) {
    const float* x    = (const float*)d_in[0];
    const int*   ei   = (const int*)  d_in[1];
    const int*   ea   = (const int*)  d_in[2];
    const float* W1   = (const float*)d_in[3];
    const float* b1   = (const float*)d_in[4];
    const float* g1   = (const float*)d_in[5];
    const float* bb1  = (const float*)d_in[6];
    const float* W2   = (const float*)d_in[7];
    const float* b2   = (const float*)d_in[8];
    const float* eps  = (const float*)d_in[9];
    const float* bond = (const float*)d_in[10];
    const float* g2   = (const float*)d_in[11];
    const float* bb2  = (const float*)d_in[12];
    float* out = (float*)d_out;

    float *p_agg, *p_y, *p_z2, *p_h;
    float *p_sum1, *p_sq1, *p_sum2, *p_sq2;
    cudaGetSymbolAddress((void**)&p_agg,  g_agg);
    cudaGetSymbolAddress((void**)&p_y,    g_y);
    cudaGetSymbolAddress((void**)&p_z2,   g_z2);
    cudaGetSymbolAddress((void**)&p_h,    g_h);
    cudaGetSymbolAddress((void**)&p_sum1, g_sum1);
    cudaGetSymbolAddress((void**)&p_sq1,  g_sq1);
    cudaGetSymbolAddress((void**)&p_sum2, g_sum2);
    cudaGetSymbolAddress((void**)&p_sq2,  g_sq2);

    const int M = NNODES;
    const int ew_blocks = (NNODES * DD / 4 + 255) / 256;
    const dim3 g1grid((M + 127) / 128, HH / 128);   // 391 x 2
    const dim3 g2grid((M + 127) / 128, DD / 128);   // 391 x 1
    const float invM = 1.f / (float)M;

    const float* hcur = x;
    for (int l = 0; l < LL; ++l) {
        zero_stats_kernel<<<1, 256>>>();
        if (l == 0)
            init_agg_kernel<<<ew_blocks, 256>>>(hcur, eps, 0);
        edge_kernel<<<1024, 256>>>(hcur, ei, ei + EDGES, ea,
                                   bond + (size_t)l * BOND_ROWS * DD);
        // GEMM1 (3x-bf16 TC, fused BN1 stats): y = agg @ W1[l] + b1[l]
        gemm_tc_kernel<DD, HH, false><<<g1grid, 256>>>(
            p_agg, W1 + (size_t)l * DD * HH, b1 + (size_t)l * HH, p_y, M,
            nullptr, nullptr, nullptr, nullptr, p_sum1, p_sq1);
        // GEMM2 (3x-bf16 TC, fused BN1+ReLU on A, fused BN2 stats)
        gemm_tc_kernel<HH, DD, true><<<g2grid, 256>>>(
            p_y, W2 + (size_t)l * HH * DD, b2 + (size_t)l * DD, p_z2, M,
            p_sum1, p_sq1, g1 + (size_t)l * HH, bb1 + (size_t)l * HH,
            p_sum2, p_sq2);
        bn2_finalize_kernel<<<1, 128>>>(g2 + (size_t)l * DD,
                                        bb2 + (size_t)l * DD, invM);
        bool last = (l == LL - 1);
        bn2_apply_kernel<<<ew_blocks, 256>>>(
            p_z2, last ? out : p_h, last ? nullptr : p_agg, eps, l + 1,
            last ? 0 : 1);
        hcur = p_h;
    }
}

// round 7
// speedup vs baseline: 1.5639x; 1.2725x over previous
#include <cuda_runtime.h>
#include <cuda_bf16.h>
#include <cstdint>

#define NNODES 50000
#define EDGES  400000
#define DD     128
#define HH     256
#define LL     5
#define BOND_ROWS 13

// ---------------- scratch (device globals; no allocation) ----------------
__device__ float g_agg[(size_t)NNODES * DD];
__device__ float g_y  [(size_t)NNODES * HH];
__device__ float g_z2 [(size_t)NNODES * DD];
__device__ float g_h  [(size_t)NNODES * DD];
__device__ float g_sum1[HH], g_sq1[HH];
__device__ float g_sum2[DD], g_sq2[DD];

// ---------------- helpers ----------------
__device__ __forceinline__ void red_add_v4(float* addr, float4 v) {
    asm volatile("red.global.add.v4.f32 [%0], {%1,%2,%3,%4};"
                 :: "l"(addr), "f"(v.x), "f"(v.y), "f"(v.z), "f"(v.w)
                 : "memory");
}
__device__ __forceinline__ float bfr(float a) {
    return __bfloat162float(__float2bfloat16_rn(a));
}
// pack two floats as bf16x2: low half = e0 (even k), high half = e1 (odd k)
__device__ __forceinline__ uint32_t packbf(float e0, float e1) {
    uint32_t r;
    asm("cvt.rn.bf16x2.f32 %0, %1, %2;" : "=r"(r) : "f"(e1), "f"(e0));
    return r;
}
__device__ __forceinline__ void mma_bf16(float* c, const uint32_t* a, const uint32_t* b) {
    asm volatile(
        "mma.sync.aligned.m16n8k16.row.col.f32.bf16.bf16.f32 "
        "{%0,%1,%2,%3}, {%4,%5,%6,%7}, {%8,%9}, {%0,%1,%2,%3};"
        : "+f"(c[0]), "+f"(c[1]), "+f"(c[2]), "+f"(c[3])
        : "r"(a[0]), "r"(a[1]), "r"(a[2]), "r"(a[3]), "r"(b[0]), "r"(b[1]));
}

// ---------------- small kernels ----------------
__global__ void zero_stats_kernel() {
    int t = threadIdx.x;
    if (t < HH) { g_sum1[t] = 0.f; g_sq1[t] = 0.f; }
    if (t < DD) { g_sum2[t] = 0.f; g_sq2[t] = 0.f; }
}

__global__ void init_agg_kernel(const float* __restrict__ h,
                                const float* __restrict__ eps, int l) {
    int i = blockIdx.x * blockDim.x + threadIdx.x;
    const int n4 = NNODES * DD / 4;
    if (i >= n4) return;
    float c = 1.f + __ldg(eps + l);
    float4 v = __ldg((const float4*)h + i);
    v.x *= c; v.y *= c; v.z *= c; v.w *= c;
    ((float4*)g_agg)[i] = v;
}

// message = relu(h[src] + bond embeddings); scatter-add into g_agg[dst]
__global__ void __launch_bounds__(256)
edge_kernel(const float* __restrict__ h,
            const int* __restrict__ src, const int* __restrict__ dst,
            const int* __restrict__ ea, const float* __restrict__ bond) {
    int warp  = (blockIdx.x * blockDim.x + threadIdx.x) >> 5;
    int lane  = threadIdx.x & 31;
    int nwarp = (gridDim.x * blockDim.x) >> 5;
    for (int e = warp; e < EDGES; e += nwarp) {
        int s  = __ldg(src + e);
        int d  = __ldg(dst + e);
        int a0 = __ldg(ea + 3 * e + 0);
        int a1 = __ldg(ea + 3 * e + 1);
        int a2 = __ldg(ea + 3 * e + 2);
        float4 v  = __ldg((const float4*)(h + (size_t)s * DD) + lane);
        float4 e0 = __ldg((const float4*)(bond + (size_t)(a0)      * DD) + lane);
        float4 e1 = __ldg((const float4*)(bond + (size_t)(5 + a1)  * DD) + lane);
        float4 e2 = __ldg((const float4*)(bond + (size_t)(11 + a2) * DD) + lane);
        v.x = fmaxf(v.x + e0.x + e1.x + e2.x, 0.f);
        v.y = fmaxf(v.y + e0.y + e1.y + e2.y, 0.f);
        v.z = fmaxf(v.z + e0.z + e1.z + e2.z, 0.f);
        v.w = fmaxf(v.w + e0.w + e1.w + e2.w, 0.f);
        red_add_v4(g_agg + (size_t)d * DD + lane * 4, v);
    }
}

// ------- 3x-bf16 split tensor-core GEMM, double-buffered, fused stats -------
// C[M,NC] = act(A)[M,K] @ B[K,NC] + bias, act = BN1+ReLU when BNA.
template<int K, int NC, bool BNA>
__global__ void __launch_bounds__(256, 2)
gemm_tc_kernel(const float* __restrict__ A, const float* __restrict__ B,
               const float* __restrict__ bias, float* __restrict__ C, int M,
               const float* __restrict__ bsum, const float* __restrict__ bsq,
               const float* __restrict__ gam,  const float* __restrict__ bet,
               float* __restrict__ osum, float* __restrict__ osq) {
    constexpr int BM = 128, BN = 128, BK = 16, K2 = BK / 2;
    constexpr int KS = BNA ? K : 1;
    // pad 8: row stride 136 == 8 (mod 32) banks -> conflict-free frag loads
    __shared__ uint32_t AsH[2][K2][BM + 8];
    __shared__ uint32_t AsL[2][K2][BM + 8];
    __shared__ uint32_t BsH[2][K2][BN + 8];
    __shared__ uint32_t BsL[2][K2][BN + 8];
    __shared__ float ssc[KS], ssh[KS];

    int tid = threadIdx.x;
    if (BNA) {
        float invM = 1.f / (float)M;
        for (int k = tid; k < K; k += 256) {
            float mu  = bsum[k] * invM;
            float var = bsq[k] * invM - mu * mu;
            float s   = gam[k] * rsqrtf(var + 1e-5f);
            ssc[k] = s;
            ssh[k] = bet[k] - mu * s;
        }
        __syncthreads();
    }

    int bm = blockIdx.x * BM;
    int bn = blockIdx.y * BN;
    int lane = tid & 31;
    int warp = tid >> 5;
    int wm = (warp & 3) * 32;
    int wn = (warp >> 2) * 64;
    int g = lane >> 2;
    int t = lane & 3;

    float acc[2][8][4];
#pragma unroll
    for (int mi = 0; mi < 2; ++mi)
#pragma unroll
        for (int ni = 0; ni < 8; ++ni)
#pragma unroll
            for (int j = 0; j < 4; ++j) acc[mi][ni][j] = 0.f;

    const int k2r = tid >> 5;      // B k-pair row 0..7
    const int cg  = tid & 31;      // B float4 col group
    const int rA0 = (tid * 2)     >> 2, cA0 = (tid * 2)     & 3;
    const int rA1 = (tid * 2 + 1) >> 2, cA1 = (tid * 2 + 1) & 3;

    float4 pa[2], pb0, pb1;

    // ---- load tile k0 into registers ----
    auto ldg_tile = [&](int k0) {
        int gr0 = bm + rA0, gr1 = bm + rA1;
        pa[0] = (gr0 < M) ? __ldg((const float4*)(A + (size_t)gr0 * K + k0 + cA0 * 4))
                          : make_float4(0.f, 0.f, 0.f, 0.f);
        pa[1] = (gr1 < M) ? __ldg((const float4*)(A + (size_t)gr1 * K + k0 + cA1 * 4))
                          : make_float4(0.f, 0.f, 0.f, 0.f);
        pb0 = __ldg((const float4*)(B + (size_t)(k0 + 2 * k2r)     * NC + bn + cg * 4));
        pb1 = __ldg((const float4*)(B + (size_t)(k0 + 2 * k2r + 1) * NC + bn + cg * 4));
    };

    // ---- convert + store registers into smem stage s ----
    auto store_tile = [&](int s, int k0) {
#pragma unroll
        for (int it = 0; it < 2; ++it) {
            int r  = it ? rA1 : rA0;
            int c4 = it ? cA1 : cA0;
            float4 v = pa[it];
            if (BNA) {
                int kk = k0 + c4 * 4;
                v.x = fmaxf(fmaf(v.x, ssc[kk + 0], ssh[kk + 0]), 0.f);
                v.y = fmaxf(fmaf(v.y, ssc[kk + 1], ssh[kk + 1]), 0.f);
                v.z = fmaxf(fmaf(v.z, ssc[kk + 2], ssh[kk + 2]), 0.f);
                v.w = fmaxf(fmaf(v.w, ssc[kk + 3], ssh[kk + 3]), 0.f);
            }
            float h0 = bfr(v.x), h1 = bfr(v.y), h2 = bfr(v.z), h3 = bfr(v.w);
            AsH[s][c4 * 2 + 0][r] = packbf(h0, h1);
            AsH[s][c4 * 2 + 1][r] = packbf(h2, h3);
            AsL[s][c4 * 2 + 0][r] = packbf(v.x - h0, v.y - h1);
            AsL[s][c4 * 2 + 1][r] = packbf(v.z - h2, v.w - h3);
        }
        float bh0 = bfr(pb0.x), bh1 = bfr(pb0.y), bh2 = bfr(pb0.z), bh3 = bfr(pb0.w);
        float ch0 = bfr(pb1.x), ch1 = bfr(pb1.y), ch2 = bfr(pb1.z), ch3 = bfr(pb1.w);
        uint4 uh, ul;
        uh.x = packbf(bh0, ch0); uh.y = packbf(bh1, ch1);
        uh.z = packbf(bh2, ch2); uh.w = packbf(bh3, ch3);
        ul.x = packbf(pb0.x - bh0, pb1.x - ch0);
        ul.y = packbf(pb0.y - bh1, pb1.y - ch1);
        ul.z = packbf(pb0.z - bh2, pb1.z - ch2);
        ul.w = packbf(pb0.w - bh3, pb1.w - ch3);
        *(uint4*)&BsH[s][k2r][cg * 4] = uh;
        *(uint4*)&BsL[s][k2r][cg * 4] = ul;
    };

    // prologue: tile 0 -> stage 0
    ldg_tile(0);
    store_tile(0, 0);
    __syncthreads();

    int s = 0;
    for (int k0 = 0; k0 < K; k0 += BK) {
        int kn = k0 + BK;
        if (kn < K) ldg_tile(kn);          // LDGs overlap with mma below

        // ---- compute on stage s: one k16 step, 3 mmas per (mi,ni) ----
        {
            uint32_t ah[2][4], al[2][4];
#pragma unroll
            for (int mi = 0; mi < 2; ++mi) {
                int row = wm + mi * 16 + g;
                ah[mi][0] = AsH[s][t][row];     ah[mi][1] = AsH[s][t][row + 8];
                ah[mi][2] = AsH[s][t + 4][row]; ah[mi][3] = AsH[s][t + 4][row + 8];
                al[mi][0] = AsL[s][t][row];     al[mi][1] = AsL[s][t][row + 8];
                al[mi][2] = AsL[s][t + 4][row]; al[mi][3] = AsL[s][t + 4][row + 8];
            }
#pragma unroll
            for (int ni = 0; ni < 8; ++ni) {
                int col = wn + ni * 8 + g;
                uint32_t bh[2], bl[2];
                bh[0] = BsH[s][t][col]; bh[1] = BsH[s][t + 4][col];
                bl[0] = BsL[s][t][col]; bl[1] = BsL[s][t + 4][col];
#pragma unroll
                for (int mi = 0; mi < 2; ++mi) {
                    mma_bf16(acc[mi][ni], ah[mi], bl);
                    mma_bf16(acc[mi][ni], al[mi], bh);
                    mma_bf16(acc[mi][ni], ah[mi], bh);
                }
            }
        }

        if (kn < K) store_tile(s ^ 1, kn); // write other stage; no conflict
        __syncthreads();                    // one barrier per iteration
        s ^= 1;
    }

    // ---- epilogue: + bias, store, fused per-column stats ----
#pragma unroll
    for (int ni = 0; ni < 8; ++ni) {
        int col = bn + wn + ni * 8 + 2 * t;
        float bx = __ldg(bias + col), by = __ldg(bias + col + 1);
        float s0 = 0.f, q0 = 0.f, s1 = 0.f, q1 = 0.f;
#pragma unroll
        for (int mi = 0; mi < 2; ++mi) {
            int row0 = bm + wm + mi * 16 + g;
            int row1 = row0 + 8;
            if (row0 < M) {
                float v0 = acc[mi][ni][0] + bx;
                float v1 = acc[mi][ni][1] + by;
                *(float2*)(C + (size_t)row0 * NC + col) = make_float2(v0, v1);
                s0 += v0; q0 = fmaf(v0, v0, q0);
                s1 += v1; q1 = fmaf(v1, v1, q1);
            }
            if (row1 < M) {
                float v2 = acc[mi][ni][2] + bx;
                float v3 = acc[mi][ni][3] + by;
                *(float2*)(C + (size_t)row1 * NC + col) = make_float2(v2, v3);
                s0 += v2; q0 = fmaf(v2, v2, q0);
                s1 += v3; q1 = fmaf(v3, v3, q1);
            }
        }
#pragma unroll
        for (int o = 4; o < 32; o <<= 1) {
            s0 += __shfl_xor_sync(0xFFFFFFFF, s0, o);
            q0 += __shfl_xor_sync(0xFFFFFFFF, q0, o);
            s1 += __shfl_xor_sync(0xFFFFFFFF, s1, o);
            q1 += __shfl_xor_sync(0xFFFFFFFF, q1, o);
        }
        if (g == 0) {
            atomicAdd(osum + col,     s0);
            atomicAdd(osq  + col,     q0);
            atomicAdd(osum + col + 1, s1);
            atomicAdd(osq  + col + 1, q1);
        }
    }
}

// out = bn2(z2) [+ relu], scale/shift computed inline from raw stats;
// optionally also write agg_next = (1+eps[lnext])*out
__global__ void bn2_apply_kernel(const float* __restrict__ z,
                                 float* __restrict__ out,
                                 float* __restrict__ agg_next,
                                 const float* __restrict__ gam,
                                 const float* __restrict__ bet,
                                 const float* __restrict__ eps, int lnext,
                                 int do_relu, float invM) {
    int i = blockIdx.x * blockDim.x + threadIdx.x;
    const int n4 = NNODES * DD / 4;
    if (i >= n4) return;
    int c = (i & (DD / 4 - 1)) << 2;
    float sc[4], sh[4];
#pragma unroll
    for (int j = 0; j < 4; ++j) {
        float mu  = g_sum2[c + j] * invM;
        float var = g_sq2[c + j] * invM - mu * mu;
        float s   = __ldg(gam + c + j) * rsqrtf(var + 1e-5f);
        sc[j] = s;
        sh[j] = __ldg(bet + c + j) - mu * s;
    }
    float4 v = __ldg((const float4*)z + i);
    v.x = fmaf(v.x, sc[0], sh[0]);
    v.y = fmaf(v.y, sc[1], sh[1]);
    v.z = fmaf(v.z, sc[2], sh[2]);
    v.w = fmaf(v.w, sc[3], sh[3]);
    if (do_relu) {
        v.x = fmaxf(v.x, 0.f); v.y = fmaxf(v.y, 0.f);
        v.z = fmaxf(v.z, 0.f); v.w = fmaxf(v.w, 0.f);
    }
    ((float4*)out)[i] = v;
    if (agg_next) {
        float ce = 1.f + __ldg(eps + lnext);
        float4 a = make_float4(v.x * ce, v.y * ce, v.z * ce, v.w * ce);
        ((float4*)agg_next)[i] = a;
    }
}

// ---------------- host launcher ----------------
extern "C" void kernel_launch(void* const* d_in, const int* in_sizes, int n_in,
                              void* d_out, int out_size) {
    const float* x    = (const float*)d_in[0];
    const int*   ei   = (const int*)  d_in[1];
    const int*   ea   = (const int*)  d_in[2];
    const float* W1   = (const float*)d_in[3];
    const float* b1   = (const float*)d_in[4];
    const float* g1   = (const float*)d_in[5];
    const float* bb1  = (const float*)d_in[6];
    const float* W2   = (const float*)d_in[7];
    const float* b2   = (const float*)d_in[8];
    const float* eps  = (const float*)d_in[9];
    const float* bond = (const float*)d_in[10];
    const float* g2   = (const float*)d_in[11];
    const float* bb2  = (const float*)d_in[12];
    float* out = (float*)d_out;

    float *p_agg, *p_y, *p_z2, *p_h;
    float *p_sum1, *p_sq1, *p_sum2, *p_sq2;
    cudaGetSymbolAddress((void**)&p_agg,  g_agg);
    cudaGetSymbolAddress((void**)&p_y,    g_y);
    cudaGetSymbolAddress((void**)&p_z2,   g_z2);
    cudaGetSymbolAddress((void**)&p_h,    g_h);
    cudaGetSymbolAddress((void**)&p_sum1, g_sum1);
    cudaGetSymbolAddress((void**)&p_sq1,  g_sq1);
    cudaGetSymbolAddress((void**)&p_sum2, g_sum2);
    cudaGetSymbolAddress((void**)&p_sq2,  g_sq2);

    const int M = NNODES;
    const int ew_blocks = (NNODES * DD / 4 + 255) / 256;
    const dim3 g1grid((M + 127) / 128, HH / 128);   // 391 x 2
    const dim3 g2grid((M + 127) / 128, DD / 128);   // 391 x 1
    const float invM = 1.f / (float)M;

    const float* hcur = x;
    for (int l = 0; l < LL; ++l) {
        zero_stats_kernel<<<1, 256>>>();
        if (l == 0)
            init_agg_kernel<<<ew_blocks, 256>>>(hcur, eps, 0);
        edge_kernel<<<1024, 256>>>(hcur, ei, ei + EDGES, ea,
                                   bond + (size_t)l * BOND_ROWS * DD);
        // GEMM1 (3x-bf16 TC, double-buffered, fused BN1 stats)
        gemm_tc_kernel<DD, HH, false><<<g1grid, 256>>>(
            p_agg, W1 + (size_t)l * DD * HH, b1 + (size_t)l * HH, p_y, M,
            nullptr, nullptr, nullptr, nullptr, p_sum1, p_sq1);
        // GEMM2 (3x-bf16 TC, fused BN1+ReLU on A, fused BN2 stats)
        gemm_tc_kernel<HH, DD, true><<<g2grid, 256>>>(
            p_y, W2 + (size_t)l * HH * DD, b2 + (size_t)l * DD, p_z2, M,
            p_sum1, p_sq1, g1 + (size_t)l * HH, bb1 + (size_t)l * HH,
            p_sum2, p_sq2);
        bool last = (l == LL - 1);
        bn2_apply_kernel<<<ew_blocks, 256>>>(
            p_z2, last ? out : p_h, last ? nullptr : p_agg,
            g2 + (size_t)l * DD, bb2 + (size_t)l * DD, eps, l + 1,
            last ? 0 : 1, invM);
        hcur = p_h;
    }
}

// round 8
// speedup vs baseline: 1.5942x; 1.0193x over previous
#include <cuda_runtime.h>
#include <cuda_bf16.h>
#include <cstdint>

#define NNODES 50000
#define EDGES  400000
#define DD     128
#define HH     256
#define LL     5
#define BOND_ROWS 13

// ---------------- scratch (device globals; no allocation) ----------------
__device__ float g_agg[(size_t)NNODES * DD];
__device__ float g_y  [(size_t)NNODES * HH];
__device__ float g_z2 [(size_t)NNODES * DD];
__device__ float g_h  [(size_t)NNODES * DD];
__device__ float g_sum1[HH], g_sq1[HH];
__device__ float g_sum2[DD], g_sq2[DD];

// ---------------- helpers ----------------
__device__ __forceinline__ void red_add_v4(float* addr, float4 v) {
    asm volatile("red.global.add.v4.f32 [%0], {%1,%2,%3,%4};"
                 :: "l"(addr), "f"(v.x), "f"(v.y), "f"(v.z), "f"(v.w)
                 : "memory");
}
__device__ __forceinline__ float bfr(float a) {
    return __bfloat162float(__float2bfloat16_rn(a));
}
// pack two floats as bf16x2: low half = e0 (even k), high half = e1 (odd k)
__device__ __forceinline__ uint32_t packbf(float e0, float e1) {
    uint32_t r;
    asm("cvt.rn.bf16x2.f32 %0, %1, %2;" : "=r"(r) : "f"(e1), "f"(e0));
    return r;
}
__device__ __forceinline__ void mma_bf16(float* c, const uint32_t* a, const uint32_t* b) {
    asm volatile(
        "mma.sync.aligned.m16n8k16.row.col.f32.bf16.bf16.f32 "
        "{%0,%1,%2,%3}, {%4,%5,%6,%7}, {%8,%9}, {%0,%1,%2,%3};"
        : "+f"(c[0]), "+f"(c[1]), "+f"(c[2]), "+f"(c[3])
        : "r"(a[0]), "r"(a[1]), "r"(a[2]), "r"(a[3]), "r"(b[0]), "r"(b[1]));
}

// ---------------- small kernels ----------------
__global__ void zero_stats_kernel() {
    int t = threadIdx.x;
    if (t < HH) { g_sum1[t] = 0.f; g_sq1[t] = 0.f; }
    if (t < DD) { g_sum2[t] = 0.f; g_sq2[t] = 0.f; }
}

__global__ void init_agg_kernel(const float* __restrict__ h,
                                const float* __restrict__ eps, int l) {
    int i = blockIdx.x * blockDim.x + threadIdx.x;
    const int n4 = NNODES * DD / 4;
    if (i >= n4) return;
    float c = 1.f + __ldg(eps + l);
    float4 v = __ldg((const float4*)h + i);
    v.x *= c; v.y *= c; v.z *= c; v.w *= c;
    ((float4*)g_agg)[i] = v;
}

// message = relu(h[src] + bond embeddings); scatter-add into g_agg[dst]
__global__ void __launch_bounds__(256)
edge_kernel(const float* __restrict__ h,
            const int* __restrict__ src, const int* __restrict__ dst,
            const int* __restrict__ ea, const float* __restrict__ bond) {
    int warp  = (blockIdx.x * blockDim.x + threadIdx.x) >> 5;
    int lane  = threadIdx.x & 31;
    int nwarp = (gridDim.x * blockDim.x) >> 5;
    for (int e = warp; e < EDGES; e += nwarp) {
        int s  = __ldg(src + e);
        int d  = __ldg(dst + e);
        int a0 = __ldg(ea + 3 * e + 0);
        int a1 = __ldg(ea + 3 * e + 1);
        int a2 = __ldg(ea + 3 * e + 2);
        float4 v  = __ldg((const float4*)(h + (size_t)s * DD) + lane);
        float4 e0 = __ldg((const float4*)(bond + (size_t)(a0)      * DD) + lane);
        float4 e1 = __ldg((const float4*)(bond + (size_t)(5 + a1)  * DD) + lane);
        float4 e2 = __ldg((const float4*)(bond + (size_t)(11 + a2) * DD) + lane);
        v.x = fmaxf(v.x + e0.x + e1.x + e2.x, 0.f);
        v.y = fmaxf(v.y + e0.y + e1.y + e2.y, 0.f);
        v.z = fmaxf(v.z + e0.z + e1.z + e2.z, 0.f);
        v.w = fmaxf(v.w + e0.w + e1.w + e2.w, 0.f);
        red_add_v4(g_agg + (size_t)d * DD + lane * 4, v);
    }
}

// ------- 3x-bf16 split tensor-core GEMM, double-buffered, fused stats -------
// C[M,NC] = act(A)[M,K] @ B[K,NC] + bias, act = BN1+ReLU when BNA.
// mma issue order is TERM-MAJOR: all (ni,mi) for ah*bl, then al*bh, then
// ah*bh -> 15 independent mmas between updates of the same accumulator.
template<int K, int NC, bool BNA>
__global__ void __launch_bounds__(256, 2)
gemm_tc_kernel(const float* __restrict__ A, const float* __restrict__ B,
               const float* __restrict__ bias, float* __restrict__ C, int M,
               const float* __restrict__ bsum, const float* __restrict__ bsq,
               const float* __restrict__ gam,  const float* __restrict__ bet,
               float* __restrict__ osum, float* __restrict__ osq) {
    constexpr int BM = 128, BN = 128, BK = 16, K2 = BK / 2;
    constexpr int KS = BNA ? K : 1;
    // pad 8: row stride 136 == 8 (mod 32) banks -> conflict-free frag loads
    __shared__ uint32_t AsH[2][K2][BM + 8];
    __shared__ uint32_t AsL[2][K2][BM + 8];
    __shared__ uint32_t BsH[2][K2][BN + 8];
    __shared__ uint32_t BsL[2][K2][BN + 8];
    __shared__ float ssc[KS], ssh[KS];

    int tid = threadIdx.x;
    if (BNA) {
        float invM = 1.f / (float)M;
        for (int k = tid; k < K; k += 256) {
            float mu  = bsum[k] * invM;
            float var = bsq[k] * invM - mu * mu;
            float s   = gam[k] * rsqrtf(var + 1e-5f);
            ssc[k] = s;
            ssh[k] = bet[k] - mu * s;
        }
        __syncthreads();
    }

    int bm = blockIdx.x * BM;
    int bn = blockIdx.y * BN;
    int lane = tid & 31;
    int warp = tid >> 5;
    int wm = (warp & 3) * 32;
    int wn = (warp >> 2) * 64;
    int g = lane >> 2;
    int t = lane & 3;

    float acc[2][8][4];
#pragma unroll
    for (int mi = 0; mi < 2; ++mi)
#pragma unroll
        for (int ni = 0; ni < 8; ++ni)
#pragma unroll
            for (int j = 0; j < 4; ++j) acc[mi][ni][j] = 0.f;

    const int k2r = tid >> 5;      // B k-pair row 0..7
    const int cg  = tid & 31;      // B float4 col group
    const int rA0 = (tid * 2)     >> 2, cA0 = (tid * 2)     & 3;
    const int rA1 = (tid * 2 + 1) >> 2, cA1 = (tid * 2 + 1) & 3;

    float4 pa[2], pb0, pb1;

    auto ldg_tile = [&](int k0) {
        int gr0 = bm + rA0, gr1 = bm + rA1;
        pa[0] = (gr0 < M) ? __ldg((const float4*)(A + (size_t)gr0 * K + k0 + cA0 * 4))
                          : make_float4(0.f, 0.f, 0.f, 0.f);
        pa[1] = (gr1 < M) ? __ldg((const float4*)(A + (size_t)gr1 * K + k0 + cA1 * 4))
                          : make_float4(0.f, 0.f, 0.f, 0.f);
        pb0 = __ldg((const float4*)(B + (size_t)(k0 + 2 * k2r)     * NC + bn + cg * 4));
        pb1 = __ldg((const float4*)(B + (size_t)(k0 + 2 * k2r + 1) * NC + bn + cg * 4));
    };

    auto store_tile = [&](int s, int k0) {
#pragma unroll
        for (int it = 0; it < 2; ++it) {
            int r  = it ? rA1 : rA0;
            int c4 = it ? cA1 : cA0;
            float4 v = pa[it];
            if (BNA) {
                int kk = k0 + c4 * 4;
                v.x = fmaxf(fmaf(v.x, ssc[kk + 0], ssh[kk + 0]), 0.f);
                v.y = fmaxf(fmaf(v.y, ssc[kk + 1], ssh[kk + 1]), 0.f);
                v.z = fmaxf(fmaf(v.z, ssc[kk + 2], ssh[kk + 2]), 0.f);
                v.w = fmaxf(fmaf(v.w, ssc[kk + 3], ssh[kk + 3]), 0.f);
            }
            float h0 = bfr(v.x), h1 = bfr(v.y), h2 = bfr(v.z), h3 = bfr(v.w);
            AsH[s][c4 * 2 + 0][r] = packbf(h0, h1);
            AsH[s][c4 * 2 + 1][r] = packbf(h2, h3);
            AsL[s][c4 * 2 + 0][r] = packbf(v.x - h0, v.y - h1);
            AsL[s][c4 * 2 + 1][r] = packbf(v.z - h2, v.w - h3);
        }
        float bh0 = bfr(pb0.x), bh1 = bfr(pb0.y), bh2 = bfr(pb0.z), bh3 = bfr(pb0.w);
        float ch0 = bfr(pb1.x), ch1 = bfr(pb1.y), ch2 = bfr(pb1.z), ch3 = bfr(pb1.w);
        uint4 uh, ul;
        uh.x = packbf(bh0, ch0); uh.y = packbf(bh1, ch1);
        uh.z = packbf(bh2, ch2); uh.w = packbf(bh3, ch3);
        ul.x = packbf(pb0.x - bh0, pb1.x - ch0);
        ul.y = packbf(pb0.y - bh1, pb1.y - ch1);
        ul.z = packbf(pb0.z - bh2, pb1.z - ch2);
        ul.w = packbf(pb0.w - bh3, pb1.w - ch3);
        *(uint4*)&BsH[s][k2r][cg * 4] = uh;
        *(uint4*)&BsL[s][k2r][cg * 4] = ul;
    };

    // prologue: tile 0 -> stage 0
    ldg_tile(0);
    store_tile(0, 0);
    __syncthreads();

    int s = 0;
    for (int k0 = 0; k0 < K; k0 += BK) {
        int kn = k0 + BK;
        if (kn < K) ldg_tile(kn);          // LDGs overlap with mma below

        // ---- load ALL fragments for stage s ----
        uint32_t ah[2][4], al[2][4];
#pragma unroll
        for (int mi = 0; mi < 2; ++mi) {
            int row = wm + mi * 16 + g;
            ah[mi][0] = AsH[s][t][row];     ah[mi][1] = AsH[s][t][row + 8];
            ah[mi][2] = AsH[s][t + 4][row]; ah[mi][3] = AsH[s][t + 4][row + 8];
            al[mi][0] = AsL[s][t][row];     al[mi][1] = AsL[s][t][row + 8];
            al[mi][2] = AsL[s][t + 4][row]; al[mi][3] = AsL[s][t + 4][row + 8];
        }
        uint32_t bh[8][2], bl[8][2];
#pragma unroll
        for (int ni = 0; ni < 8; ++ni) {
            int col = wn + ni * 8 + g;
            bh[ni][0] = BsH[s][t][col]; bh[ni][1] = BsH[s][t + 4][col];
            bl[ni][0] = BsL[s][t][col]; bl[ni][1] = BsL[s][t + 4][col];
        }

        // ---- term-major mma issue: 16 independent mmas per term ----
#pragma unroll
        for (int ni = 0; ni < 8; ++ni)
#pragma unroll
            for (int mi = 0; mi < 2; ++mi)
                mma_bf16(acc[mi][ni], ah[mi], bl[ni]);
#pragma unroll
        for (int ni = 0; ni < 8; ++ni)
#pragma unroll
            for (int mi = 0; mi < 2; ++mi)
                mma_bf16(acc[mi][ni], al[mi], bh[ni]);
#pragma unroll
        for (int ni = 0; ni < 8; ++ni)
#pragma unroll
            for (int mi = 0; mi < 2; ++mi)
                mma_bf16(acc[mi][ni], ah[mi], bh[ni]);

        if (kn < K) store_tile(s ^ 1, kn);
        __syncthreads();
        s ^= 1;
    }

    // ---- epilogue: + bias, store, fused per-column stats ----
#pragma unroll
    for (int ni = 0; ni < 8; ++ni) {
        int col = bn + wn + ni * 8 + 2 * t;
        float bx = __ldg(bias + col), by = __ldg(bias + col + 1);
        float s0 = 0.f, q0 = 0.f, s1 = 0.f, q1 = 0.f;
#pragma unroll
        for (int mi = 0; mi < 2; ++mi) {
            int row0 = bm + wm + mi * 16 + g;
            int row1 = row0 + 8;
            if (row0 < M) {
                float v0 = acc[mi][ni][0] + bx;
                float v1 = acc[mi][ni][1] + by;
                *(float2*)(C + (size_t)row0 * NC + col) = make_float2(v0, v1);
                s0 += v0; q0 = fmaf(v0, v0, q0);
                s1 += v1; q1 = fmaf(v1, v1, q1);
            }
            if (row1 < M) {
                float v2 = acc[mi][ni][2] + bx;
                float v3 = acc[mi][ni][3] + by;
                *(float2*)(C + (size_t)row1 * NC + col) = make_float2(v2, v3);
                s0 += v2; q0 = fmaf(v2, v2, q0);
                s1 += v3; q1 = fmaf(v3, v3, q1);
            }
        }
#pragma unroll
        for (int o = 4; o < 32; o <<= 1) {
            s0 += __shfl_xor_sync(0xFFFFFFFF, s0, o);
            q0 += __shfl_xor_sync(0xFFFFFFFF, q0, o);
            s1 += __shfl_xor_sync(0xFFFFFFFF, s1, o);
            q1 += __shfl_xor_sync(0xFFFFFFFF, q1, o);
        }
        if (g == 0) {
            atomicAdd(osum + col,     s0);
            atomicAdd(osq  + col,     q0);
            atomicAdd(osum + col + 1, s1);
            atomicAdd(osq  + col + 1, q1);
        }
    }
}

// out = bn2(z2) [+ relu], scale/shift computed inline from raw stats;
// optionally also write agg_next = (1+eps[lnext])*out
__global__ void bn2_apply_kernel(const float* __restrict__ z,
                                 float* __restrict__ out,
                                 float* __restrict__ agg_next,
                                 const float* __restrict__ gam,
                                 const float* __restrict__ bet,
                                 const float* __restrict__ eps, int lnext,
                                 int do_relu, float invM) {
    int i = blockIdx.x * blockDim.x + threadIdx.x;
    const int n4 = NNODES * DD / 4;
    if (i >= n4) return;
    int c = (i & (DD / 4 - 1)) << 2;
    float sc[4], sh[4];
#pragma unroll
    for (int j = 0; j < 4; ++j) {
        float mu  = g_sum2[c + j] * invM;
        float var = g_sq2[c + j] * invM - mu * mu;
        float s   = __ldg(gam + c + j) * rsqrtf(var + 1e-5f);
        sc[j] = s;
        sh[j] = __ldg(bet + c + j) - mu * s;
    }
    float4 v = __ldg((const float4*)z + i);
    v.x = fmaf(v.x, sc[0], sh[0]);
    v.y = fmaf(v.y, sc[1], sh[1]);
    v.z = fmaf(v.z, sc[2], sh[2]);
    v.w = fmaf(v.w, sc[3], sh[3]);
    if (do_relu) {
        v.x = fmaxf(v.x, 0.f); v.y = fmaxf(v.y, 0.f);
        v.z = fmaxf(v.z, 0.f); v.w = fmaxf(v.w, 0.f);
    }
    ((float4*)out)[i] = v;
    if (agg_next) {
        float ce = 1.f + __ldg(eps + lnext);
        float4 a = make_float4(v.x * ce, v.y * ce, v.z * ce, v.w * ce);
        ((float4*)agg_next)[i] = a;
    }
}

// ---------------- host launcher ----------------
extern "C" void kernel_launch(void* const* d_in, const int* in_sizes, int n_in,
                              void* d_out, int out_size) {
    const float* x    = (const float*)d_in[0];
    const int*   ei   = (const int*)  d_in[1];
    const int*   ea   = (const int*)  d_in[2];
    const float* W1   = (const float*)d_in[3];
    const float* b1   = (const float*)d_in[4];
    const float* g1   = (const float*)d_in[5];
    const float* bb1  = (const float*)d_in[6];
    const float* W2   = (const float*)d_in[7];
    const float* b2   = (const float*)d_in[8];
    const float* eps  = (const float*)d_in[9];
    const float* bond = (const float*)d_in[10];
    const float* g2   = (const float*)d_in[11];
    const float* bb2  = (const float*)d_in[12];
    float* out = (float*)d_out;

    float *p_agg, *p_y, *p_z2, *p_h;
    float *p_sum1, *p_sq1, *p_sum2, *p_sq2;
    cudaGetSymbolAddress((void**)&p_agg,  g_agg);
    cudaGetSymbolAddress((void**)&p_y,    g_y);
    cudaGetSymbolAddress((void**)&p_z2,   g_z2);
    cudaGetSymbolAddress((void**)&p_h,    g_h);
    cudaGetSymbolAddress((void**)&p_sum1, g_sum1);
    cudaGetSymbolAddress((void**)&p_sq1,  g_sq1);
    cudaGetSymbolAddress((void**)&p_sum2, g_sum2);
    cudaGetSymbolAddress((void**)&p_sq2,  g_sq2);

    const int M = NNODES;
    const int ew_blocks = (NNODES * DD / 4 + 255) / 256;
    const dim3 g1grid((M + 127) / 128, HH / 128);   // 391 x 2
    const dim3 g2grid((M + 127) / 128, DD / 128);   // 391 x 1
    const float invM = 1.f / (float)M;

    const float* hcur = x;
    for (int l = 0; l < LL; ++l) {
        zero_stats_kernel<<<1, 256>>>();
        if (l == 0)
            init_agg_kernel<<<ew_blocks, 256>>>(hcur, eps, 0);
        edge_kernel<<<1024, 256>>>(hcur, ei, ei + EDGES, ea,
                                   bond + (size_t)l * BOND_ROWS * DD);
        // GEMM1 (3x-bf16 TC, double-buffered, fused BN1 stats)
        gemm_tc_kernel<DD, HH, false><<<g1grid, 256>>>(
            p_agg, W1 + (size_t)l * DD * HH, b1 + (size_t)l * HH, p_y, M,
            nullptr, nullptr, nullptr, nullptr, p_sum1, p_sq1);
        // GEMM2 (3x-bf16 TC, fused BN1+ReLU on A, fused BN2 stats)
        gemm_tc_kernel<HH, DD, true><<<g2grid, 256>>>(
            p_y, W2 + (size_t)l * HH * DD, b2 + (size_t)l * DD, p_z2, M,
            p_sum1, p_sq1, g1 + (size_t)l * HH, bb1 + (size_t)l * HH,
            p_sum2, p_sq2);
        bool last = (l == LL - 1);
        bn2_apply_kernel<<<ew_blocks, 256>>>(
            p_z2, last ? out : p_h, last ? nullptr : p_agg,
            g2 + (size_t)l * DD, bb2 + (size_t)l * DD, eps, l + 1,
            last ? 0 : 1, invM);
        hcur = p_h;
    }
}

// round 10
// speedup vs baseline: 1.7851x; 1.1198x over previous
#include <cuda_runtime.h>
#include <cuda_bf16.h>
#include <cstdint>

#define NNODES 50000
#define EDGES  400000
#define DD     128
#define HH     256
#define LL     5
#define BOND_ROWS 13
#define NCODE  60   // 5*6*2 distinct bond-attr combinations

// ---------------- scratch (device globals; no allocation) ----------------
__device__ float g_agg[(size_t)NNODES * DD];
__device__ float g_y  [(size_t)NNODES * HH];
__device__ float g_z2 [(size_t)NNODES * DD];
__device__ float g_h  [(size_t)NNODES * DD];
__device__ float g_sum1[HH], g_sq1[HH];
__device__ float g_sum2[DD], g_sq2[DD];
__device__ float g_btab[NCODE * DD];     // per-layer combined bond table

// ---------------- helpers ----------------
__device__ __forceinline__ void red_add_v4(float* addr, float4 v) {
    asm volatile("red.global.add.v4.f32 [%0], {%1,%2,%3,%4};"
                 :: "l"(addr), "f"(v.x), "f"(v.y), "f"(v.z), "f"(v.w)
                 : "memory");
}
__device__ __forceinline__ float bfr(float a) {
    return __bfloat162float(__float2bfloat16_rn(a));
}
__device__ __forceinline__ uint32_t packbf(float e0, float e1) {
    uint32_t r;
    asm("cvt.rn.bf16x2.f32 %0, %1, %2;" : "=r"(r) : "f"(e1), "f"(e0));
    return r;
}
__device__ __forceinline__ void mma_bf16(float* c, const uint32_t* a, const uint32_t* b) {
    asm volatile(
        "mma.sync.aligned.m16n8k16.row.col.f32.bf16.bf16.f32 "
        "{%0,%1,%2,%3}, {%4,%5,%6,%7}, {%8,%9}, {%0,%1,%2,%3};"
        : "+f"(c[0]), "+f"(c[1]), "+f"(c[2]), "+f"(c[3])
        : "r"(a[0]), "r"(a[1]), "r"(a[2]), "r"(a[3]), "r"(b[0]), "r"(b[1]));
}

// ---------------- small kernels ----------------
// combined bond table for layer l: table[code] = b0[a0] + b1[a1] + b2[a2]
__global__ void bond_table_kernel(const float* __restrict__ bond) {
    int code = blockIdx.x;           // 0..59
    int d    = threadIdx.x;          // 0..127
    int a0 = code / 12, a1 = (code / 2) % 6, a2 = code & 1;
    g_btab[code * DD + d] = __ldg(bond + (size_t)a0 * DD + d)
                          + __ldg(bond + (size_t)(5 + a1) * DD + d)
                          + __ldg(bond + (size_t)(11 + a2) * DD + d);
}

__global__ void init_agg_kernel(const float* __restrict__ h,
                                const float* __restrict__ eps, int l) {
    int i = blockIdx.x * blockDim.x + threadIdx.x;
    const int n4 = NNODES * DD / 4;
    if (i >= n4) return;
    float c = 1.f + __ldg(eps + l);
    float4 v = __ldg((const float4*)h + i);
    v.x *= c; v.y *= c; v.z *= c; v.w *= c;
    ((float4*)g_agg)[i] = v;
}

// message = relu(h[src] + table[code]); scatter-add into g_agg[dst].
// One warp per edge, 2-edge software pipeline. Block 0 also zeroes BN stats.
__global__ void __launch_bounds__(256)
edge_kernel(const float* __restrict__ h,
            const int* __restrict__ src, const int* __restrict__ dst,
            const int* __restrict__ ea) {
    if (blockIdx.x == 0) {
        int t = threadIdx.x;
        if (t < HH) { g_sum1[t] = 0.f; g_sq1[t] = 0.f; }
        if (t < DD) { g_sum2[t] = 0.f; g_sq2[t] = 0.f; }
    }
    int warp  = (blockIdx.x * blockDim.x + threadIdx.x) >> 5;
    int lane  = threadIdx.x & 31;
    int nwarp = (gridDim.x * blockDim.x) >> 5;

    int e = warp;
    for (; e + nwarp < EDGES; e += 2 * nwarp) {
        int e1 = e + nwarp;
        int s0 = __ldg(src + e),  d0 = __ldg(dst + e);
        int s1 = __ldg(src + e1), d1 = __ldg(dst + e1);
        int c0 = (__ldg(ea + 3 * e)  * 6 + __ldg(ea + 3 * e  + 1)) * 2 + __ldg(ea + 3 * e  + 2);
        int c1 = (__ldg(ea + 3 * e1) * 6 + __ldg(ea + 3 * e1 + 1)) * 2 + __ldg(ea + 3 * e1 + 2);
        float4 v0 = __ldg((const float4*)(h + (size_t)s0 * DD) + lane);
        float4 v1 = __ldg((const float4*)(h + (size_t)s1 * DD) + lane);
        float4 t0 = __ldg((const float4*)(g_btab + (size_t)c0 * DD) + lane);
        float4 t1 = __ldg((const float4*)(g_btab + (size_t)c1 * DD) + lane);
        v0.x = fmaxf(v0.x + t0.x, 0.f); v0.y = fmaxf(v0.y + t0.y, 0.f);
        v0.z = fmaxf(v0.z + t0.z, 0.f); v0.w = fmaxf(v0.w + t0.w, 0.f);
        v1.x = fmaxf(v1.x + t1.x, 0.f); v1.y = fmaxf(v1.y + t1.y, 0.f);
        v1.z = fmaxf(v1.z + t1.z, 0.f); v1.w = fmaxf(v1.w + t1.w, 0.f);
        red_add_v4(g_agg + (size_t)d0 * DD + lane * 4, v0);
        red_add_v4(g_agg + (size_t)d1 * DD + lane * 4, v1);
    }
    if (e < EDGES) {
        int s0 = __ldg(src + e), d0 = __ldg(dst + e);
        int c0 = (__ldg(ea + 3 * e) * 6 + __ldg(ea + 3 * e + 1)) * 2 + __ldg(ea + 3 * e + 2);
        float4 v0 = __ldg((const float4*)(h + (size_t)s0 * DD) + lane);
        float4 t0 = __ldg((const float4*)(g_btab + (size_t)c0 * DD) + lane);
        v0.x = fmaxf(v0.x + t0.x, 0.f); v0.y = fmaxf(v0.y + t0.y, 0.f);
        v0.z = fmaxf(v0.z + t0.z, 0.f); v0.w = fmaxf(v0.w + t0.w, 0.f);
        red_add_v4(g_agg + (size_t)d0 * DD + lane * 4, v0);
    }
}

// ------- 3x-bf16 split tensor-core GEMM, double-buffered, fused stats -------
// (unchanged from R8 — mma.sync path is at its floor)
template<int K, int NC, bool BNA>
__global__ void __launch_bounds__(256, 2)
gemm_tc_kernel(const float* __restrict__ A, const float* __restrict__ B,
               const float* __restrict__ bias, float* __restrict__ C, int M,
               const float* __restrict__ bsum, const float* __restrict__ bsq,
               const float* __restrict__ gam,  const float* __restrict__ bet,
               float* __restrict__ osum, float* __restrict__ osq) {
    constexpr int BM = 128, BN = 128, BK = 16, K2 = BK / 2;
    constexpr int KS = BNA ? K : 1;
    __shared__ uint32_t AsH[2][K2][BM + 8];
    __shared__ uint32_t AsL[2][K2][BM + 8];
    __shared__ uint32_t BsH[2][K2][BN + 8];
    __shared__ uint32_t BsL[2][K2][BN + 8];
    __shared__ float ssc[KS], ssh[KS];

    int tid = threadIdx.x;
    if (BNA) {
        float invM = 1.f / (float)M;
        for (int k = tid; k < K; k += 256) {
            float mu  = bsum[k] * invM;
            float var = bsq[k] * invM - mu * mu;
            float s   = gam[k] * rsqrtf(var + 1e-5f);
            ssc[k] = s;
            ssh[k] = bet[k] - mu * s;
        }
        __syncthreads();
    }

    int bm = blockIdx.x * BM;
    int bn = blockIdx.y * BN;
    int lane = tid & 31;
    int warp = tid >> 5;
    int wm = (warp & 3) * 32;
    int wn = (warp >> 2) * 64;
    int g = lane >> 2;
    int t = lane & 3;

    float acc[2][8][4];
#pragma unroll
    for (int mi = 0; mi < 2; ++mi)
#pragma unroll
        for (int ni = 0; ni < 8; ++ni)
#pragma unroll
            for (int j = 0; j < 4; ++j) acc[mi][ni][j] = 0.f;

    const int k2r = tid >> 5;
    const int cg  = tid & 31;
    const int rA0 = (tid * 2)     >> 2, cA0 = (tid * 2)     & 3;
    const int rA1 = (tid * 2 + 1) >> 2, cA1 = (tid * 2 + 1) & 3;

    float4 pa[2], pb0, pb1;

    auto ldg_tile = [&](int k0) {
        int gr0 = bm + rA0, gr1 = bm + rA1;
        pa[0] = (gr0 < M) ? __ldg((const float4*)(A + (size_t)gr0 * K + k0 + cA0 * 4))
                          : make_float4(0.f, 0.f, 0.f, 0.f);
        pa[1] = (gr1 < M) ? __ldg((const float4*)(A + (size_t)gr1 * K + k0 + cA1 * 4))
                          : make_float4(0.f, 0.f, 0.f, 0.f);
        pb0 = __ldg((const float4*)(B + (size_t)(k0 + 2 * k2r)     * NC + bn + cg * 4));
        pb1 = __ldg((const float4*)(B + (size_t)(k0 + 2 * k2r + 1) * NC + bn + cg * 4));
    };

    auto store_tile = [&](int s, int k0) {
#pragma unroll
        for (int it = 0; it < 2; ++it) {
            int r  = it ? rA1 : rA0;
            int c4 = it ? cA1 : cA0;
            float4 v = pa[it];
            if (BNA) {
                int kk = k0 + c4 * 4;
                v.x = fmaxf(fmaf(v.x, ssc[kk + 0], ssh[kk + 0]), 0.f);
                v.y = fmaxf(fmaf(v.y, ssc[kk + 1], ssh[kk + 1]), 0.f);
                v.z = fmaxf(fmaf(v.z, ssc[kk + 2], ssh[kk + 2]), 0.f);
                v.w = fmaxf(fmaf(v.w, ssc[kk + 3], ssh[kk + 3]), 0.f);
            }
            float h0 = bfr(v.x), h1 = bfr(v.y), h2 = bfr(v.z), h3 = bfr(v.w);
            AsH[s][c4 * 2 + 0][r] = packbf(h0, h1);
            AsH[s][c4 * 2 + 1][r] = packbf(h2, h3);
            AsL[s][c4 * 2 + 0][r] = packbf(v.x - h0, v.y - h1);
            AsL[s][c4 * 2 + 1][r] = packbf(v.z - h2, v.w - h3);
        }
        float bh0 = bfr(pb0.x), bh1 = bfr(pb0.y), bh2 = bfr(pb0.z), bh3 = bfr(pb0.w);
        float ch0 = bfr(pb1.x), ch1 = bfr(pb1.y), ch2 = bfr(pb1.z), ch3 = bfr(pb1.w);
        uint4 uh, ul;
        uh.x = packbf(bh0, ch0); uh.y = packbf(bh1, ch1);
        uh.z = packbf(bh2, ch2); uh.w = packbf(bh3, ch3);
        ul.x = packbf(pb0.x - bh0, pb1.x - ch0);
        ul.y = packbf(pb0.y - bh1, pb1.y - ch1);
        ul.z = packbf(pb0.z - bh2, pb1.z - ch2);
        ul.w = packbf(pb0.w - bh3, pb1.w - ch3);
        *(uint4*)&BsH[s][k2r][cg * 4] = uh;
        *(uint4*)&BsL[s][k2r][cg * 4] = ul;
    };

    ldg_tile(0);
    store_tile(0, 0);
    __syncthreads();

    int s = 0;
    for (int k0 = 0; k0 < K; k0 += BK) {
        int kn = k0 + BK;
        if (kn < K) ldg_tile(kn);

        uint32_t ah[2][4], al[2][4];
#pragma unroll
        for (int mi = 0; mi < 2; ++mi) {
            int row = wm + mi * 16 + g;
            ah[mi][0] = AsH[s][t][row];     ah[mi][1] = AsH[s][t][row + 8];
            ah[mi][2] = AsH[s][t + 4][row]; ah[mi][3] = AsH[s][t + 4][row + 8];
            al[mi][0] = AsL[s][t][row];     al[mi][1] = AsL[s][t][row + 8];
            al[mi][2] = AsL[s][t + 4][row]; al[mi][3] = AsL[s][t + 4][row + 8];
        }
        uint32_t bh[8][2], bl[8][2];
#pragma unroll
        for (int ni = 0; ni < 8; ++ni) {
            int col = wn + ni * 8 + g;
            bh[ni][0] = BsH[s][t][col]; bh[ni][1] = BsH[s][t + 4][col];
            bl[ni][0] = BsL[s][t][col]; bl[ni][1] = BsL[s][t + 4][col];
        }
#pragma unroll
        for (int ni = 0; ni < 8; ++ni)
#pragma unroll
            for (int mi = 0; mi < 2; ++mi)
                mma_bf16(acc[mi][ni], ah[mi], bl[ni]);
#pragma unroll
        for (int ni = 0; ni < 8; ++ni)
#pragma unroll
            for (int mi = 0; mi < 2; ++mi)
                mma_bf16(acc[mi][ni], al[mi], bh[ni]);
#pragma unroll
        for (int ni = 0; ni < 8; ++ni)
#pragma unroll
            for (int mi = 0; mi < 2; ++mi)
                mma_bf16(acc[mi][ni], ah[mi], bh[ni]);

        if (kn < K) store_tile(s ^ 1, kn);
        __syncthreads();
        s ^= 1;
    }

#pragma unroll
    for (int ni = 0; ni < 8; ++ni) {
        int col = bn + wn + ni * 8 + 2 * t;
        float bx = __ldg(bias + col), by = __ldg(bias + col + 1);
        float s0 = 0.f, q0 = 0.f, s1 = 0.f, q1 = 0.f;
#pragma unroll
        for (int mi = 0; mi < 2; ++mi) {
            int row0 = bm + wm + mi * 16 + g;
            int row1 = row0 + 8;
            if (row0 < M) {
                float v0 = acc[mi][ni][0] + bx;
                float v1 = acc[mi][ni][1] + by;
                *(float2*)(C + (size_t)row0 * NC + col) = make_float2(v0, v1);
                s0 += v0; q0 = fmaf(v0, v0, q0);
                s1 += v1; q1 = fmaf(v1, v1, q1);
            }
            if (row1 < M) {
                float v2 = acc[mi][ni][2] + bx;
                float v3 = acc[mi][ni][3] + by;
                *(float2*)(C + (size_t)row1 * NC + col) = make_float2(v2, v3);
                s0 += v2; q0 = fmaf(v2, v2, q0);
                s1 += v3; q1 = fmaf(v3, v3, q1);
            }
        }
#pragma unroll
        for (int o = 4; o < 32; o <<= 1) {
            s0 += __shfl_xor_sync(0xFFFFFFFF, s0, o);
            q0 += __shfl_xor_sync(0xFFFFFFFF, q0, o);
            s1 += __shfl_xor_sync(0xFFFFFFFF, s1, o);
            q1 += __shfl_xor_sync(0xFFFFFFFF, q1, o);
        }
        if (g == 0) {
            atomicAdd(osum + col,     s0);
            atomicAdd(osq  + col,     q0);
            atomicAdd(osum + col + 1, s1);
            atomicAdd(osq  + col + 1, q1);
        }
    }
}

// out = bn2(z2) [+ relu]; scale/shift staged in smem (128 rsqrt per block);
// each block covers 32 rows (1024 float4). Optional agg_next write.
__global__ void __launch_bounds__(256)
bn2_apply_kernel(const float* __restrict__ z,
                 float* __restrict__ out,
                 float* __restrict__ agg_next,
                 const float* __restrict__ gam,
                 const float* __restrict__ bet,
                 const float* __restrict__ eps, int lnext,
                 int do_relu, float invM) {
    __shared__ float sc[DD], sh[DD];
    int tid = threadIdx.x;
    if (tid < DD) {
        float mu  = g_sum2[tid] * invM;
        float var = g_sq2[tid] * invM - mu * mu;
        float s   = __ldg(gam + tid) * rsqrtf(var + 1e-5f);
        sc[tid] = s;
        sh[tid] = __ldg(bet + tid) - mu * s;
    }
    __syncthreads();
    float ce = 1.f + __ldg(eps + lnext);
    const int n4 = NNODES * DD / 4;
    int base = blockIdx.x * 1024;
#pragma unroll
    for (int j = 0; j < 4; ++j) {
        int i = base + j * 256 + tid;
        if (i >= n4) break;
        int c = (i & (DD / 4 - 1)) << 2;
        float4 v = __ldg((const float4*)z + i);
        v.x = fmaf(v.x, sc[c + 0], sh[c + 0]);
        v.y = fmaf(v.y, sc[c + 1], sh[c + 1]);
        v.z = fmaf(v.z, sc[c + 2], sh[c + 2]);
        v.w = fmaf(v.w, sc[c + 3], sh[c + 3]);
        if (do_relu) {
            v.x = fmaxf(v.x, 0.f); v.y = fmaxf(v.y, 0.f);
            v.z = fmaxf(v.z, 0.f); v.w = fmaxf(v.w, 0.f);
        }
        ((float4*)out)[i] = v;
        if (agg_next) {
            float4 a = make_float4(v.x * ce, v.y * ce, v.z * ce, v.w * ce);
            ((float4*)agg_next)[i] = a;
        }
    }
}

// ---------------- host launcher ----------------
extern "C" void kernel_launch(void* const* d_in, const int* in_sizes, int n_in,
                              void* d_out, int out_size) {
    const float* x    = (const float*)d_in[0];
    const int*   ei   = (const int*)  d_in[1];
    const int*   ea   = (const int*)  d_in[2];
    const float* W1   = (const float*)d_in[3];
    const float* b1   = (const float*)d_in[4];
    const float* g1   = (const float*)d_in[5];
    const float* bb1  = (const float*)d_in[6];
    const float* W2   = (const float*)d_in[7];
    const float* b2   = (const float*)d_in[8];
    const float* eps  = (const float*)d_in[9];
    const float* bond = (const float*)d_in[10];
    const float* g2   = (const float*)d_in[11];
    const float* bb2  = (const float*)d_in[12];
    float* out = (float*)d_out;

    float *p_agg, *p_y, *p_z2, *p_h;
    float *p_sum1, *p_sq1, *p_sum2, *p_sq2;
    cudaGetSymbolAddress((void**)&p_agg,  g_agg);
    cudaGetSymbolAddress((void**)&p_y,    g_y);
    cudaGetSymbolAddress((void**)&p_z2,   g_z2);
    cudaGetSymbolAddress((void**)&p_h,    g_h);
    cudaGetSymbolAddress((void**)&p_sum1, g_sum1);
    cudaGetSymbolAddress((void**)&p_sq1,  g_sq1);
    cudaGetSymbolAddress((void**)&p_sum2, g_sum2);
    cudaGetSymbolAddress((void**)&p_sq2,  g_sq2);

    const int M = NNODES;
    const int ew_blocks = (NNODES * DD / 4 + 255) / 256;        // 6250
    const int bn_blocks = (NNODES * DD / 4 + 1023) / 1024;      // 1563
    const dim3 g1grid((M + 127) / 128, HH / 128);   // 391 x 2
    const dim3 g2grid((M + 127) / 128, DD / 128);   // 391 x 1
    const float invM = 1.f / (float)M;

    const float* hcur = x;
    for (int l = 0; l < LL; ++l) {
        bond_table_kernel<<<NCODE, DD>>>(bond + (size_t)l * BOND_ROWS * DD);
        if (l == 0)
            init_agg_kernel<<<ew_blocks, 256>>>(hcur, eps, 0);
        edge_kernel<<<1024, 256>>>(hcur, ei, ei + EDGES, ea);
        // GEMM1 (3x-bf16 TC, double-buffered, fused BN1 stats)
        gemm_tc_kernel<DD, HH, false><<<g1grid, 256>>>(
            p_agg, W1 + (size_t)l * DD * HH, b1 + (size_t)l * HH, p_y, M,
            nullptr, nullptr, nullptr, nullptr, p_sum1, p_sq1);
        // GEMM2 (3x-bf16 TC, fused BN1+ReLU on A, fused BN2 stats)
        gemm_tc_kernel<HH, DD, true><<<g2grid, 256>>>(
            p_y, W2 + (size_t)l * HH * DD, b2 + (size_t)l * DD, p_z2, M,
            p_sum1, p_sq1, g1 + (size_t)l * HH, bb1 + (size_t)l * HH,
            p_sum2, p_sq2);
        bool last = (l == LL - 1);
        bn2_apply_kernel<<<bn_blocks, 256>>>(
            p_z2, last ? out : p_h, last ? nullptr : p_agg,
            g2 + (size_t)l * DD, bb2 + (size_t)l * DD, eps, l + 1,
            last ? 0 : 1, invM);
        hcur = p_h;
    }
}